// round 15
// baseline (speedup 1.0000x reference)
#include <cuda_runtime.h>
#include <cuda_bf16.h>
#include <math.h>
#include <stdint.h>

#define TT 8
#define FIN 128
#define HH 128
#define NMAX 50048
#define EMAX 800000
#define G4 (4*HH)

// ---------------- device scratch (allocation-free rule: __device__ globals) ----
static __device__ __nv_bfloat16 g_xh[(size_t)TT * NMAX * HH];
static __device__ __nv_bfloat16 g_xl[(size_t)TT * NMAX * HH];
static __device__ __nv_bfloat16 g_fh[(size_t)TT * NMAX * HH];   // feats hi
static __device__ __nv_bfloat16 g_fl[(size_t)TT * NMAX * HH];   // feats lo
static __device__ __nv_bfloat16 g_b2h[(size_t)TT * NMAX * HH];  // gcn layer1 out hi
static __device__ __nv_bfloat16 g_b2l[(size_t)TT * NMAX * HH];
static __device__ float g_nis[(size_t)TT * NMAX];               // deg then deg^{-1/2}
static __device__ float g_hlin[(size_t)TT * NMAX * HH];         // batched x@W+b
static __device__ int   g_offs[(size_t)TT * (NMAX + 1)];        // CSR row offsets
static __device__ int   g_cursor[(size_t)TT * NMAX];            // fill cursors
static __device__ int   g_csr[(size_t)TT * EMAX];               // src ids grouped by dst
static __device__ float g_state[(size_t)4 * NMAX * HH];         // h1a,c1,h2a,c2
static __device__ __nv_bfloat16 g_h1h_a[(size_t)NMAX * HH];
static __device__ __nv_bfloat16 g_h1l_a[(size_t)NMAX * HH];
static __device__ __nv_bfloat16 g_h1h_b[(size_t)NMAX * HH];
static __device__ __nv_bfloat16 g_h1l_b[(size_t)NMAX * HH];
static __device__ __nv_bfloat16 g_h2h_a[(size_t)NMAX * HH];
static __device__ __nv_bfloat16 g_h2l_a[(size_t)NMAX * HH];
static __device__ __nv_bfloat16 g_h2h_b[(size_t)NMAX * HH];
static __device__ __nv_bfloat16 g_h2l_b[(size_t)NMAX * HH];
// LSTM weights, gate-interleaved cols [n'=4j+g][k], K-major, K=256 = [Wih ; Whh]
static __device__ __nv_bfloat16 g_B1h[512 * 256];
static __device__ __nv_bfloat16 g_B1l[512 * 256];
static __device__ __nv_bfloat16 g_B2h[512 * 256];
static __device__ __nv_bfloat16 g_B2l[512 * 256];
static __device__ __nv_bfloat16 g_GW1h[128 * 128];              // gcn W^T [n][k]
static __device__ __nv_bfloat16 g_GW1l[128 * 128];
static __device__ __nv_bfloat16 g_GW2h[128 * 128];
static __device__ __nv_bfloat16 g_GW2l[128 * 128];
static __device__ float g_bias1[G4];
static __device__ float g_bias2[G4];
static __device__ int   g_idx64;

// ---------------- helpers ----------------
__device__ __forceinline__ int load_idx(const void* p, size_t off) {
    return g_idx64 ? (int)((const long long*)p)[off] : ((const int*)p)[off];
}
__device__ __forceinline__ float sigm(float x) { return 1.0f / (1.0f + expf(-x)); }

__device__ __forceinline__ void split_bf16(float v, __nv_bfloat16& h, __nv_bfloat16& l) {
    h = __float2bfloat16(v);
    l = __float2bfloat16(v - __bfloat162float(h));
}

__device__ __forceinline__ void cpasync16(uint32_t dst, const void* src, int sz) {
    asm volatile("cp.async.cg.shared.global [%0], [%1], 16, %2;\n" :: "r"(dst), "l"(src), "r"(sz));
}
__device__ __forceinline__ void cp_commit() { asm volatile("cp.async.commit_group;\n"); }
__device__ __forceinline__ void cp_wait1() { asm volatile("cp.async.wait_group 1;\n"); }

__device__ __forceinline__ uint32_t swz(uint32_t o) { return o ^ ((o >> 3) & 0x10); }

__device__ __forceinline__ void ldsm4(uint32_t* r, uint32_t addr) {
    asm volatile("ldmatrix.sync.aligned.m8n8.x4.shared.b16 {%0,%1,%2,%3}, [%4];"
                 : "=r"(r[0]), "=r"(r[1]), "=r"(r[2]), "=r"(r[3]) : "r"(addr));
}

__device__ __forceinline__ void mma_bf16(float* d, const uint32_t* a, const uint32_t* b) {
    asm volatile(
        "mma.sync.aligned.m16n8k16.row.col.f32.bf16.bf16.f32 "
        "{%0,%1,%2,%3}, {%4,%5,%6,%7}, {%8,%9}, {%0,%1,%2,%3};\n"
        : "+f"(d[0]), "+f"(d[1]), "+f"(d[2]), "+f"(d[3])
        : "r"(a[0]), "r"(a[1]), "r"(a[2]), "r"(a[3]), "r"(b[0]), "r"(b[1]));
}

// ---------------- prep kernels ----------------
__global__ void detect_idx_kernel(const void* ei) {
    const int* p = (const int*)ei;
    int s = 0;
    for (int i = 1; i < 257; i += 2) s |= p[i];
    g_idx64 = (s == 0) ? 1 : 0;
}

__global__ void split_x_kernel(const float* __restrict__ x, size_t total) {
    for (size_t i = (size_t)blockIdx.x * blockDim.x + threadIdx.x; i < total;
         i += (size_t)gridDim.x * blockDim.x) {
        split_bf16(x[i], g_xh[i], g_xl[i]);
    }
}

__global__ void prep_weights_kernel(const float* __restrict__ gw1, const float* __restrict__ gw2,
                                    const float* __restrict__ wih1, const float* __restrict__ whh1,
                                    const float* __restrict__ bih1, const float* __restrict__ bhh1,
                                    const float* __restrict__ wih2, const float* __restrict__ whh2,
                                    const float* __restrict__ bih2, const float* __restrict__ bhh2) {
    int idx = blockIdx.x * blockDim.x + threadIdx.x;
    if (idx < 512 * 256) {
        int n = idx >> 8;       // gate-interleaved col 4j+g
        int k = idx & 255;
        int j = n >> 2, g = n & 3;
        int orow = g * 128 + j;
        float v1, v2;
        if (k < 128) { v1 = wih1[orow * 128 + k];         v2 = wih2[orow * 128 + k]; }
        else         { v1 = whh1[orow * 128 + (k - 128)]; v2 = whh2[orow * 128 + (k - 128)]; }
        split_bf16(v1, g_B1h[idx], g_B1l[idx]);
        split_bf16(v2, g_B2h[idx], g_B2l[idx]);
    }
    if (idx < 128 * 128) {
        int n = idx >> 7, k = idx & 127;
        split_bf16(gw1[k * 128 + n], g_GW1h[idx], g_GW1l[idx]);
        split_bf16(gw2[k * 128 + n], g_GW2h[idx], g_GW2l[idx]);
    }
    if (idx < 512) {
        int j = idx >> 2, g = idx & 3;
        int orow = g * 128 + j;
        g_bias1[idx] = bih1[orow] + bhh1[orow];
        g_bias2[idx] = bih2[orow] + bhh2[orow];
    }
}

// ---------------- GCN: degree, CSR build, gather ----------------
__global__ void deg_all_kernel(const void* __restrict__ ei, int E, int N, float* __restrict__ deg) {
    long long i = (long long)blockIdx.x * blockDim.x + threadIdx.x;
    if (i >= (long long)TT * E) return;
    int t = (int)(i / E);
    int e = (int)(i - (long long)t * E);
    int d = load_idx(ei, (size_t)t * 2 * E + E + e);
    atomicAdd(&deg[(size_t)t * N + d], 1.0f);
}

// one block per t: exclusive scan of integer degree counts -> CSR offsets
__global__ void scan_offsets_kernel(const float* __restrict__ deg, int* __restrict__ offs, int N) {
    __shared__ int sm[1024];
    __shared__ int sbase;
    const int t = blockIdx.x;
    if (threadIdx.x == 0) sbase = 0;
    __syncthreads();
    const float* dt = deg + (size_t)t * N;
    int* ot = offs + (size_t)t * (N + 1);
    for (int base = 0; base < N; base += 1024) {
        int i = base + threadIdx.x;
        int v = (i < N) ? (int)dt[i] : 0;
        sm[threadIdx.x] = v;
        __syncthreads();
        for (int off = 1; off < 1024; off <<= 1) {
            int x = (threadIdx.x >= off) ? sm[threadIdx.x - off] : 0;
            __syncthreads();
            sm[threadIdx.x] += x;
            __syncthreads();
        }
        int incl = sm[threadIdx.x];
        if (i < N) ot[i] = sbase + incl - v;
        __syncthreads();
        if (threadIdx.x == 1023) sbase += sm[1023];
        __syncthreads();
    }
    if (threadIdx.x == 0) ot[N] = sbase;
}

__global__ void csr_fill_kernel(const void* __restrict__ ei, int E, int N,
                                const int* __restrict__ offs, int* __restrict__ cursor,
                                int* __restrict__ csr) {
    long long i = (long long)blockIdx.x * blockDim.x + threadIdx.x;
    if (i >= (long long)TT * E) return;
    int t = (int)(i / E);
    int e = (int)(i - (long long)t * E);
    int s = load_idx(ei, (size_t)t * 2 * E + e);
    int d = load_idx(ei, (size_t)t * 2 * E + E + e);
    int pos = atomicAdd(&cursor[(size_t)t * N + d], 1);
    csr[(size_t)t * E + offs[(size_t)t * (N + 1) + d] + pos] = s;
}

__global__ void nis_all_kernel(float* __restrict__ nis, long long total) {
    long long i = (long long)blockIdx.x * blockDim.x + threadIdx.x;
    if (i < total) nis[i] = rsqrtf(nis[i] + 1.0f);
}

// Batched (grid.y = t) CSR gather: warp handles TWO dst nodes, interleaved chains.
__global__ void gather_combine_all_kernel(const int* __restrict__ csr, const int* __restrict__ offs,
                                          const float* __restrict__ nis, const float* __restrict__ hlin,
                                          __nv_bfloat16* __restrict__ oh, __nv_bfloat16* __restrict__ ol,
                                          int N, int E) {
    const int t = blockIdx.y;
    const int* csr_t = csr + (size_t)t * E;
    const int* offs_t = offs + (size_t)t * (N + 1);
    const float* nis_t = nis + (size_t)t * N;
    const float* hlin_t = hlin + (size_t)t * N * HH;
    __nv_bfloat16* oh_t = oh + (size_t)t * N * HH;
    __nv_bfloat16* ol_t = ol + (size_t)t * N * HH;

    int w = (blockIdx.x * blockDim.x + threadIdx.x) >> 5;
    int lane = threadIdx.x & 31;
    int n0 = 2 * w;
    if (n0 >= N) return;
    int n1 = n0 + 1;
    bool has1 = (n1 < N);

    int b0 = offs_t[n0], e0 = offs_t[n0 + 1];
    int b1 = has1 ? offs_t[n1] : 0, e1 = has1 ? offs_t[n1 + 1] : 0;
    int len0 = e0 - b0, len1 = e1 - b1;
    int L = (len0 > len1) ? len0 : len1;

    float4 a0 = make_float4(0.f, 0.f, 0.f, 0.f);
    float4 a1 = make_float4(0.f, 0.f, 0.f, 0.f);
    for (int i = 0; i < L; i++) {
        if (i < len0) {
            int s = csr_t[b0 + i];
            float ns = nis_t[s];
            float4 v = ((const float4*)(hlin_t + (size_t)s * HH))[lane];
            a0.x += v.x * ns; a0.y += v.y * ns; a0.z += v.z * ns; a0.w += v.w * ns;
        }
        if (i < len1) {
            int s = csr_t[b1 + i];
            float ns = nis_t[s];
            float4 v = ((const float4*)(hlin_t + (size_t)s * HH))[lane];
            a1.x += v.x * ns; a1.y += v.y * ns; a1.z += v.z * ns; a1.w += v.w * ns;
        }
    }

    {
        float nd = nis_t[n0];
        float4 self = ((const float4*)(hlin_t + (size_t)n0 * HH))[lane];
        float4 r;
        r.x = fmaxf(nd * (a0.x + nd * self.x), 0.0f);
        r.y = fmaxf(nd * (a0.y + nd * self.y), 0.0f);
        r.z = fmaxf(nd * (a0.z + nd * self.z), 0.0f);
        r.w = fmaxf(nd * (a0.w + nd * self.w), 0.0f);
        __nv_bfloat16 h0, l0, h1, l1, h2, l2, h3, l3;
        split_bf16(r.x, h0, l0); split_bf16(r.y, h1, l1);
        split_bf16(r.z, h2, l2); split_bf16(r.w, h3, l3);
        __nv_bfloat162* dh = (__nv_bfloat162*)(oh_t + (size_t)n0 * HH + lane * 4);
        __nv_bfloat162* dl = (__nv_bfloat162*)(ol_t + (size_t)n0 * HH + lane * 4);
        dh[0] = __nv_bfloat162(h0, h1); dh[1] = __nv_bfloat162(h2, h3);
        dl[0] = __nv_bfloat162(l0, l1); dl[1] = __nv_bfloat162(l2, l3);
    }
    if (has1) {
        float nd = nis_t[n1];
        float4 self = ((const float4*)(hlin_t + (size_t)n1 * HH))[lane];
        float4 r;
        r.x = fmaxf(nd * (a1.x + nd * self.x), 0.0f);
        r.y = fmaxf(nd * (a1.y + nd * self.y), 0.0f);
        r.z = fmaxf(nd * (a1.z + nd * self.z), 0.0f);
        r.w = fmaxf(nd * (a1.w + nd * self.w), 0.0f);
        __nv_bfloat16 h0, l0, h1, l1, h2, l2, h3, l3;
        split_bf16(r.x, h0, l0); split_bf16(r.y, h1, l1);
        split_bf16(r.z, h2, l2); split_bf16(r.w, h3, l3);
        __nv_bfloat162* dh = (__nv_bfloat162*)(oh_t + (size_t)n1 * HH + lane * 4);
        __nv_bfloat162* dl = (__nv_bfloat162*)(ol_t + (size_t)n1 * HH + lane * 4);
        dh[0] = __nv_bfloat162(h0, h1); dh[1] = __nv_bfloat162(h2, h3);
        dl[0] = __nv_bfloat162(l0, l1); dl[1] = __nv_bfloat162(l2, l3);
    }
}

// ---------------- emulated-fp32 GEMM via bf16x2 (3-term) tensor mma ----------
// K chunked by 32 as TWO 16-wide sub-tiles per stage; one wait+sync per 32 K.
// LSTM epilogue: shfl-pair gate exchange (no smem staging, no extra syncs).
#define BM 128
#define BN 128
#define SUBB 16384      // one 16-wide sub-tile: Ah(4K)+Al(4K)+Bh(4K)+Bl(4K)
#define STAGE2 (2*SUBB) // 32-wide stage
#define GSMEM (3*STAGE2)

struct GemmPtrs {
    const __nv_bfloat16 *A1h, *A1l, *A2h, *A2l, *Bth, *Btl;
    const float* bias;
    float* cstate;
    float* hout;
    __nv_bfloat16 *houth, *houtl;
};

template<bool LSTM>
__device__ __forceinline__ void gemm_core(
    int M, int Nt, int K, GemmPtrs P, float* __restrict__ Cout, char* smemc) {

    const uint32_t smemBase = (uint32_t)__cvta_generic_to_shared(smemc);

    const int tid = threadIdx.x;
    const int lane = tid & 31;
    const int wid = tid >> 5;
    const int wm = wid >> 2;          // 0..1
    const int wn = wid & 3;           // 0..3
    const int row0 = blockIdx.y * BM;
    const int col0 = blockIdx.x * BN;

    float acc[4][4][4];
#pragma unroll
    for (int i = 0; i < 4; i++)
#pragma unroll
        for (int j = 0; j < 4; j++)
#pragma unroll
            for (int v = 0; v < 4; v++) acc[i][j][v] = 0.0f;

    const int CH = K / 32;

    const int lrow = tid >> 1;        // 0..127
    const int lh = tid & 1;
    const uint32_t dOff = swz((uint32_t)(lrow * 32 + lh * 16));

    auto load_chunk = [&](int ch, int buf) {
        const int gr = row0 + lrow;
        const int pa = (gr < M) ? 16 : 0;
#pragma unroll
        for (int sub = 0; sub < 2; sub++) {
            const int k0 = ch * 32 + sub * 16;
            const __nv_bfloat16 *Aph, *Apl;
            int kk;
            if (k0 < 128) { Aph = P.A1h; Apl = P.A1l; kk = k0; }
            else          { Aph = P.A2h; Apl = P.A2l; kk = k0 - 128; }
            const uint32_t base = smemBase + buf * STAGE2 + sub * SUBB;
            const size_t aoff = (size_t)gr * 128 + kk + lh * 8;
            cpasync16(base + dOff,         Aph + aoff, pa);
            cpasync16(base + 4096 + dOff,  Apl + aoff, pa);
            const size_t boff = (size_t)(col0 + lrow) * K + k0 + lh * 8;
            cpasync16(base + 8192 + dOff,  P.Bth + boff, 16);
            cpasync16(base + 12288 + dOff, P.Btl + boff, 16);
        }
    };

    const int a_r = lane & 15;
    const int a_h = lane >> 4;
    const int b_n = (lane & 7) + ((lane >> 4) << 3);
    const int b_h = (lane >> 3) & 1;

    load_chunk(0, 0);
    cp_commit();
    if (CH > 1) { load_chunk(1, 1); }
    cp_commit();

    int buf = 0;
    for (int ch = 0; ch < CH; ch++) {
        cp_wait1();
        __syncthreads();
#pragma unroll
        for (int sub = 0; sub < 2; sub++) {
            const uint32_t base = smemBase + buf * STAGE2 + sub * SUBB;
            uint32_t ah[4][4], al[4][4], bh[4][2], bl[4][2];
#pragma unroll
            for (int mf = 0; mf < 4; mf++) {
                uint32_t ao = swz((uint32_t)((wm * 64 + mf * 16 + a_r) * 32 + a_h * 16));
                ldsm4(ah[mf], base + ao);
                ldsm4(al[mf], base + 4096 + ao);
            }
#pragma unroll
            for (int nf2 = 0; nf2 < 2; nf2++) {
                uint32_t bo = swz((uint32_t)((wn * 32 + nf2 * 16 + b_n) * 32 + b_h * 16));
                uint32_t t4[4];
                ldsm4(t4, base + 8192 + bo);
                bh[2 * nf2][0] = t4[0]; bh[2 * nf2][1] = t4[1];
                bh[2 * nf2 + 1][0] = t4[2]; bh[2 * nf2 + 1][1] = t4[3];
                ldsm4(t4, base + 12288 + bo);
                bl[2 * nf2][0] = t4[0]; bl[2 * nf2][1] = t4[1];
                bl[2 * nf2 + 1][0] = t4[2]; bl[2 * nf2 + 1][1] = t4[3];
            }
#pragma unroll
            for (int mf = 0; mf < 4; mf++)
#pragma unroll
                for (int nf = 0; nf < 4; nf++)
                    mma_bf16(acc[mf][nf], ah[mf], bh[nf]);
#pragma unroll
            for (int mf = 0; mf < 4; mf++)
#pragma unroll
                for (int nf = 0; nf < 4; nf++)
                    mma_bf16(acc[mf][nf], ah[mf], bl[nf]);
#pragma unroll
            for (int mf = 0; mf < 4; mf++)
#pragma unroll
                for (int nf = 0; nf < 4; nf++)
                    mma_bf16(acc[mf][nf], al[mf], bh[nf]);
        }

        if (ch + 2 < CH) {
            int nbuf = buf + 2; if (nbuf >= 3) nbuf -= 3;
            load_chunk(ch + 2, nbuf);
        }
        cp_commit();
        if (++buf == 3) buf = 0;
    }
    // no trailing sync: epilogues below do not touch shared memory

    if (!LSTM) {
#pragma unroll
        for (int mf = 0; mf < 4; mf++) {
            int gr = row0 + wm * 64 + mf * 16 + (lane >> 2);
#pragma unroll
            for (int nf = 0; nf < 4; nf++) {
                int gc = col0 + wn * 32 + nf * 8 + 2 * (lane & 3);
                float b0 = P.bias[gc], b1 = P.bias[gc + 1];
                if (gr < M) {
                    float2 v = make_float2(acc[mf][nf][0] + b0, acc[mf][nf][1] + b1);
                    *(float2*)(Cout + (size_t)gr * Nt + gc) = v;
                }
                if (gr + 8 < M) {
                    float2 v = make_float2(acc[mf][nf][2] + b0, acc[mf][nf][3] + b1);
                    *(float2*)(Cout + (size_t)(gr + 8) * Nt + gc) = v;
                }
            }
        }
    } else {
        // shfl-pair epilogue. With gate-interleaved cols (4j+{i,f,g,o}):
        //   even lane (lane&1==0): cols 4j,4j+1   -> (i,f) of quad j
        //   odd lane  (lane&1==1): cols 4j+2,4j+3 -> (g,o) of same quad j
        // Exchange across lane^1: even computes cell for row r, odd for row r+8.
        const bool evenLane = !(lane & 1);
#pragma unroll
        for (int mf = 0; mf < 4; mf++) {
#pragma unroll
            for (int nf = 0; nf < 4; nf++) {
                int gc = col0 + wn * 32 + nf * 8 + 2 * (lane & 3);
                float v0 = acc[mf][nf][0] + P.bias[gc];
                float v1 = acc[mf][nf][1] + P.bias[gc + 1];
                float v2 = acc[mf][nf][2] + P.bias[gc];
                float v3 = acc[mf][nf][3] + P.bias[gc + 1];
                // even sends (i,f) of row r+8; odd sends (g,o) of row r
                float s0 = __shfl_xor_sync(0xFFFFFFFFu, evenLane ? v2 : v0, 1);
                float s1 = __shfl_xor_sync(0xFFFFFFFFu, evenLane ? v3 : v1, 1);
                float gi = evenLane ? v0 : s0;
                float gf = evenLane ? v1 : s1;
                float gg = evenLane ? s0 : v2;
                float go = evenLane ? s1 : v3;
                int r = (lane >> 2) + (evenLane ? 0 : 8);
                int node = row0 + wm * 64 + mf * 16 + r;
                int j = (col0 + wn * 32 + nf * 8 + (((lane & 3) & 2) << 1)) >> 2;
                if (node < M) {
                    size_t ci = (size_t)node * HH + j;
                    float cn = sigm(gf) * P.cstate[ci] + sigm(gi) * tanhf(gg);
                    P.cstate[ci] = cn;
                    float hv = sigm(go) * tanhf(cn);
                    if (P.hout) P.hout[ci] = hv;
                    split_bf16(hv, P.houth[ci], P.houtl[ci]);
                }
            }
        }
    }
}

// out_proj body (shared): warp computes out[n] = h2 . w + b for grid-stride nodes
__device__ __forceinline__ void out_proj_body(
    const __nv_bfloat16* __restrict__ h2h, const __nv_bfloat16* __restrict__ h2l,
    const float* __restrict__ w, const float* __restrict__ b,
    float* __restrict__ out, int n, int warpId, int nWarps, int lane) {
    float4 wv = ((const float4*)w)[lane];
    float bv = b[0];
    for (int node = warpId; node < n; node += nWarps) {
        const __nv_bfloat162* ph = (const __nv_bfloat162*)(h2h + (size_t)node * HH + lane * 4);
        const __nv_bfloat162* pl = (const __nv_bfloat162*)(h2l + (size_t)node * HH + lane * 4);
        __nv_bfloat162 hh0 = ph[0], hh1 = ph[1], ll0 = pl[0], ll1 = pl[1];
        float v0 = __bfloat162float(hh0.x) + __bfloat162float(ll0.x);
        float v1 = __bfloat162float(hh0.y) + __bfloat162float(ll0.y);
        float v2 = __bfloat162float(hh1.x) + __bfloat162float(ll1.x);
        float v3 = __bfloat162float(hh1.y) + __bfloat162float(ll1.y);
        float s = v0 * wv.x + v1 * wv.y + v2 * wv.z + v3 * wv.w;
#pragma unroll
        for (int off = 16; off; off >>= 1) s += __shfl_xor_sync(0xFFFFFFFFu, s, off);
        if (lane == 0) out[node] = s + bv;
    }
}

template<bool LSTM>
__global__ void __launch_bounds__(256) mma_gemm_kernel(
    int M, int Nt, int K, GemmPtrs P, float* Cout) {
    extern __shared__ char smemc[];
    gemm_core<LSTM>(M, Nt, K, P, Cout, smemc);
}

// merged launch: z < nGemm -> GEMM slice (z==0 -> PA, z==1 -> PB);
// z == nGemm -> out_proj of the PREVIOUS timestep (planes already final).
__global__ void __launch_bounds__(256) lstm_pair_kernel(
    int M, int nGemm, GemmPtrs PA, GemmPtrs PB,
    const __nv_bfloat16* oph, const __nv_bfloat16* opl,
    const float* ow, const float* ob, float* ovec) {
    extern __shared__ char smemc[];
    if ((int)blockIdx.z >= nGemm) {
        const int bid = blockIdx.y * gridDim.x + blockIdx.x;
        const int warpId = bid * (blockDim.x >> 5) + (threadIdx.x >> 5);
        const int nWarps = gridDim.x * gridDim.y * (blockDim.x >> 5);
        out_proj_body(oph, opl, ow, ob, ovec, M, warpId, nWarps, threadIdx.x & 31);
        return;
    }
    gemm_core<true>(M, G4, 256, blockIdx.z ? PB : PA, nullptr, smemc);
}

// standalone out_proj (final timestep)
__global__ void out_proj_kernel(const __nv_bfloat16* __restrict__ h2h,
                                const __nv_bfloat16* __restrict__ h2l,
                                const float* __restrict__ w,
                                const float* __restrict__ b, float* __restrict__ out, int n) {
    int warpId = (blockIdx.x * blockDim.x + threadIdx.x) >> 5;
    int nWarps = (gridDim.x * blockDim.x) >> 5;
    out_proj_body(h2h, h2l, w, b, out, n, warpId, nWarps, threadIdx.x & 31);
}

__global__ void copy_states_kernel(const float* __restrict__ st, float* __restrict__ out, size_t nh) {
    size_t i = (size_t)blockIdx.x * blockDim.x + threadIdx.x;
    size_t total = 4 * nh;
    for (; i < total; i += (size_t)gridDim.x * blockDim.x) out[i] = st[i];
}

// ---------------- host launch ----------------
static inline int cdiv(int a, int b) { return (a + b - 1) / b; }
#define SYM(var, sym) cudaGetSymbolAddress((void**)&var, sym)

extern "C" void kernel_launch(void* const* d_in, const int* in_sizes, int n_in,
                              void* d_out, int out_size) {
    const float* x    = (const float*)d_in[0];
    const void*  ei   = d_in[1];
    const float* gw1  = (const float*)d_in[2];
    const float* gb1  = (const float*)d_in[3];
    const float* gw2  = (const float*)d_in[4];
    const float* gb2  = (const float*)d_in[5];
    const float* wih1 = (const float*)d_in[6];
    const float* whh1 = (const float*)d_in[7];
    const float* bih1 = (const float*)d_in[8];
    const float* bhh1 = (const float*)d_in[9];
    const float* wih2 = (const float*)d_in[10];
    const float* whh2 = (const float*)d_in[11];
    const float* bih2 = (const float*)d_in[12];
    const float* bhh2 = (const float*)d_in[13];
    const float* outw = (const float*)d_in[14];
    const float* outb = (const float*)d_in[15];

    const int N = in_sizes[0] / (TT * FIN);
    const int E = in_sizes[1] / (2 * TT);
    float* out = (float*)d_out;

    __nv_bfloat16 *xh, *xl, *fh, *fl, *b2h, *b2l;
    __nv_bfloat16 *h1h_a, *h1l_a, *h1h_b, *h1l_b, *h2h_a, *h2l_a, *h2h_b, *h2l_b;
    __nv_bfloat16 *B1h, *B1l, *B2h, *B2l, *GW1h, *GW1l, *GW2h, *GW2l;
    float *nis, *hlin, *state, *bias1, *bias2;
    int *offs, *cursor, *csr;
    SYM(xh, g_xh); SYM(xl, g_xl); SYM(fh, g_fh); SYM(fl, g_fl);
    SYM(b2h, g_b2h); SYM(b2l, g_b2l);
    SYM(h1h_a, g_h1h_a); SYM(h1l_a, g_h1l_a); SYM(h1h_b, g_h1h_b); SYM(h1l_b, g_h1l_b);
    SYM(h2h_a, g_h2h_a); SYM(h2l_a, g_h2l_a); SYM(h2h_b, g_h2h_b); SYM(h2l_b, g_h2l_b);
    SYM(B1h, g_B1h); SYM(B1l, g_B1l); SYM(B2h, g_B2h); SYM(B2l, g_B2l);
    SYM(GW1h, g_GW1h); SYM(GW1l, g_GW1l); SYM(GW2h, g_GW2h); SYM(GW2l, g_GW2l);
    SYM(nis, g_nis); SYM(hlin, g_hlin);
    SYM(offs, g_offs); SYM(cursor, g_cursor); SYM(csr, g_csr);
    SYM(state, g_state); SYM(bias1, g_bias1); SYM(bias2, g_bias2);

    const size_t NH = (size_t)N * HH;
    const long long TN = (long long)TT * N;

    const int mbA = (int)((TN + BM - 1) / BM);  // 3125
    const int mbL = cdiv(N, BM);                // 391
    const int gx = cdiv(cdiv(N, 2) * 32, 256);  // gather grid.x (2 nodes/warp)

    cudaFuncSetAttribute(mma_gemm_kernel<false>, cudaFuncAttributeMaxDynamicSharedMemorySize, GSMEM);
    cudaFuncSetAttribute(mma_gemm_kernel<true>,  cudaFuncAttributeMaxDynamicSharedMemorySize, GSMEM);
    cudaFuncSetAttribute(lstm_pair_kernel,       cudaFuncAttributeMaxDynamicSharedMemorySize, GSMEM);

    GemmPtrs P{};

    // launch order keeps GCN L1 GEMM at #5 (ncu sentinel across rounds)
    detect_idx_kernel<<<1, 1>>>(ei);                                            // 1
    prep_weights_kernel<<<cdiv(512 * 256, 256), 256>>>(gw1, gw2, wih1, whh1,    // 2
                                                       bih1, bhh1, wih2, whh2, bih2, bhh2);
    split_x_kernel<<<2048, 256>>>(x, (size_t)TN * FIN);                         // 3
    cudaMemsetAsync(nis, 0, TN * sizeof(float));                                // 4

    // -------- GCN layer 1 GEMM (batched over all t) --------                  // 5
    P = GemmPtrs{xh, xl, nullptr, nullptr, GW1h, GW1l, gb1, nullptr, nullptr, nullptr, nullptr};
    mma_gemm_kernel<false><<<dim3(1, mbA), 256, GSMEM>>>((int)TN, HH, 128, P, hlin);

    // -------- degrees -> CSR offsets -> fill -> nis --------
    deg_all_kernel<<<(unsigned)(((long long)TT * E + 255) / 256), 256>>>(ei, E, N, nis);
    scan_offsets_kernel<<<TT, 1024>>>(nis, offs, N);
    cudaMemsetAsync(cursor, 0, (size_t)TT * N * sizeof(int));
    csr_fill_kernel<<<(unsigned)(((long long)TT * E + 255) / 256), 256>>>(ei, E, N, offs, cursor, csr);
    nis_all_kernel<<<(unsigned)((TN + 255) / 256), 256>>>(nis, TN);

    // -------- GCN layer 1 gather (batched over t, 2 nodes/warp) --------
    gather_combine_all_kernel<<<dim3(gx, TT), 256>>>(csr, offs, nis, hlin, b2h, b2l, N, E);

    // -------- GCN layer 2 --------
    P = GemmPtrs{b2h, b2l, nullptr, nullptr, GW2h, GW2l, gb2, nullptr, nullptr, nullptr, nullptr};
    mma_gemm_kernel<false><<<dim3(1, mbA), 256, GSMEM>>>((int)TN, HH, 128, P, hlin);
    gather_combine_all_kernel<<<dim3(gx, TT), 256>>>(csr, offs, nis, hlin, fh, fl, N, E);

    // -------- LSTM over time (merged pairs + folded out_proj slices) --------
    cudaMemsetAsync(state, 0, 4 * NH * sizeof(float));
    cudaMemsetAsync(h1h_a, 0, NH * sizeof(__nv_bfloat16));
    cudaMemsetAsync(h1l_a, 0, NH * sizeof(__nv_bfloat16));
    cudaMemsetAsync(h2h_a, 0, NH * sizeof(__nv_bfloat16));
    cudaMemsetAsync(h2l_a, 0, NH * sizeof(__nv_bfloat16));

    float* h1a = state;               // final h1 (t=7 odd writes A bufs)
    float* c1  = state + NH;
    float* h2a = state + 2 * NH;
    float* c2  = state + 3 * NH;

    auto L1ptrs = [&](int t) -> GemmPtrs {
        const int odd = t & 1;
        return GemmPtrs{
            fh + (size_t)t * NH, fl + (size_t)t * NH,
            odd ? h1h_b : h1h_a, odd ? h1l_b : h1l_a,   // h1_{t-1} in
            B1h, B1l, bias1, c1,
            (t == TT - 1) ? h1a : nullptr,
            odd ? h1h_a : h1h_b, odd ? h1l_a : h1l_b};  // h1_t out
    };
    auto L2ptrs = [&](int t) -> GemmPtrs {
        const int odd = t & 1;
        return GemmPtrs{
            odd ? h1h_a : h1h_b, odd ? h1l_a : h1l_b,   // h1_t in
            odd ? h2h_b : h2h_a, odd ? h2l_b : h2l_a,   // h2_{t-1} in
            B2h, B2l, bias2, c2,
            (t == TT - 1) ? h2a : nullptr,
            odd ? h2h_a : h2h_b, odd ? h2l_a : h2l_b};  // h2_t out
    };
    auto h2h_of = [&](int t) { return (t & 1) ? h2h_a : h2h_b; };
    auto h2l_of = [&](int t) { return (t & 1) ? h2l_a : h2l_b; };

    // t=0 layer 1
    mma_gemm_kernel<true><<<dim3(4, mbL), 256, GSMEM>>>(N, G4, 256, L1ptrs(0), nullptr);
    for (int t = 0; t < TT; t++) {
        const bool hasOp = (t >= 1);   // out_proj(t-1) rides along
        const __nv_bfloat16* oph = hasOp ? h2h_of(t - 1) : nullptr;
        const __nv_bfloat16* opl = hasOp ? h2l_of(t - 1) : nullptr;
        float* ovec = hasOp ? out + (size_t)(t - 1) * N : nullptr;
        if (t + 1 < TT) {
            // z0: layer2(t), z1: layer1(t+1), z2 (if hasOp): out_proj(t-1)
            lstm_pair_kernel<<<dim3(4, mbL, hasOp ? 3 : 2), 256, GSMEM>>>(
                N, 2, L2ptrs(t), L1ptrs(t + 1), oph, opl, outw, outb, ovec);
        } else {
            // final: z0: layer2(7), z1: out_proj(6)
            lstm_pair_kernel<<<dim3(4, mbL, 2), 256, GSMEM>>>(
                N, 1, L2ptrs(t), L2ptrs(t), oph, opl, outw, outb, ovec);
        }
    }
    // out_proj(7)
    out_proj_kernel<<<cdiv(N * 32, 256), 256>>>(h2h_of(TT - 1), h2l_of(TT - 1),
                                                outw, outb, out + (size_t)(TT - 1) * N, N);

    // -------- tail: h1, c1, h2, c2 (t=7 odd -> finals in buf A = state) ------
    copy_states_kernel<<<1024, 256>>>(state, out + (size_t)TT * N, NH);
}

// round 16
// speedup vs baseline: 1.1677x; 1.1677x over previous
#include <cuda_runtime.h>
#include <cuda_bf16.h>
#include <math.h>
#include <stdint.h>

#define TT 8
#define FIN 128
#define HH 128
#define NMAX 50048
#define EMAX 800000
#define G4 (4*HH)

// ---------------- device scratch (allocation-free rule: __device__ globals) ----
static __device__ __nv_bfloat16 g_xh[(size_t)TT * NMAX * HH];
static __device__ __nv_bfloat16 g_xl[(size_t)TT * NMAX * HH];
static __device__ __nv_bfloat16 g_fh[(size_t)TT * NMAX * HH];   // feats hi
static __device__ __nv_bfloat16 g_fl[(size_t)TT * NMAX * HH];   // feats lo
static __device__ __nv_bfloat16 g_b2h[(size_t)TT * NMAX * HH];  // gcn layer1 out hi
static __device__ __nv_bfloat16 g_b2l[(size_t)TT * NMAX * HH];
static __device__ float g_nis[(size_t)TT * NMAX];               // deg then deg^{-1/2}
static __device__ float g_hlin[(size_t)TT * NMAX * HH];         // batched x@W+b
static __device__ int   g_offs[(size_t)TT * (NMAX + 1)];        // CSR row offsets
static __device__ int   g_cursor[(size_t)TT * NMAX];            // fill cursors
static __device__ int   g_csr[(size_t)TT * EMAX];               // src ids grouped by dst
static __device__ float g_state[(size_t)4 * NMAX * HH];         // h1a,c1,h2a,c2
static __device__ __nv_bfloat16 g_h1h_a[(size_t)NMAX * HH];
static __device__ __nv_bfloat16 g_h1l_a[(size_t)NMAX * HH];
static __device__ __nv_bfloat16 g_h1h_b[(size_t)NMAX * HH];
static __device__ __nv_bfloat16 g_h1l_b[(size_t)NMAX * HH];
static __device__ __nv_bfloat16 g_h2h_a[(size_t)NMAX * HH];
static __device__ __nv_bfloat16 g_h2l_a[(size_t)NMAX * HH];
static __device__ __nv_bfloat16 g_h2h_b[(size_t)NMAX * HH];
static __device__ __nv_bfloat16 g_h2l_b[(size_t)NMAX * HH];
// LSTM weights, gate-interleaved cols [n'=4j+g][k], K-major, K=256 = [Wih ; Whh]
static __device__ __nv_bfloat16 g_B1h[512 * 256];
static __device__ __nv_bfloat16 g_B1l[512 * 256];
static __device__ __nv_bfloat16 g_B2h[512 * 256];
static __device__ __nv_bfloat16 g_B2l[512 * 256];
static __device__ __nv_bfloat16 g_GW1h[128 * 128];              // gcn W^T [n][k]
static __device__ __nv_bfloat16 g_GW1l[128 * 128];
static __device__ __nv_bfloat16 g_GW2h[128 * 128];
static __device__ __nv_bfloat16 g_GW2l[128 * 128];
static __device__ float g_bias1[G4];
static __device__ float g_bias2[G4];
static __device__ int   g_idx64;

// ---------------- helpers ----------------
__device__ __forceinline__ int load_idx(const void* p, size_t off) {
    return g_idx64 ? (int)((const long long*)p)[off] : ((const int*)p)[off];
}
__device__ __forceinline__ float sigm(float x) { return 1.0f / (1.0f + expf(-x)); }

__device__ __forceinline__ void split_bf16(float v, __nv_bfloat16& h, __nv_bfloat16& l) {
    h = __float2bfloat16(v);
    l = __float2bfloat16(v - __bfloat162float(h));
}

__device__ __forceinline__ void cpasync16(uint32_t dst, const void* src, int sz) {
    asm volatile("cp.async.cg.shared.global [%0], [%1], 16, %2;\n" :: "r"(dst), "l"(src), "r"(sz));
}
__device__ __forceinline__ void cp_commit() { asm volatile("cp.async.commit_group;\n"); }
__device__ __forceinline__ void cp_wait1() { asm volatile("cp.async.wait_group 1;\n"); }

__device__ __forceinline__ uint32_t swz(uint32_t o) { return o ^ ((o >> 3) & 0x10); }

__device__ __forceinline__ void ldsm4(uint32_t* r, uint32_t addr) {
    asm volatile("ldmatrix.sync.aligned.m8n8.x4.shared.b16 {%0,%1,%2,%3}, [%4];"
                 : "=r"(r[0]), "=r"(r[1]), "=r"(r[2]), "=r"(r[3]) : "r"(addr));
}

__device__ __forceinline__ void mma_bf16(float* d, const uint32_t* a, const uint32_t* b) {
    asm volatile(
        "mma.sync.aligned.m16n8k16.row.col.f32.bf16.bf16.f32 "
        "{%0,%1,%2,%3}, {%4,%5,%6,%7}, {%8,%9}, {%0,%1,%2,%3};\n"
        : "+f"(d[0]), "+f"(d[1]), "+f"(d[2]), "+f"(d[3])
        : "r"(a[0]), "r"(a[1]), "r"(a[2]), "r"(a[3]), "r"(b[0]), "r"(b[1]));
}

// ---------------- prep kernels ----------------
__global__ void detect_idx_kernel(const void* ei) {
    const int* p = (const int*)ei;
    int s = 0;
    for (int i = 1; i < 257; i += 2) s |= p[i];
    g_idx64 = (s == 0) ? 1 : 0;
}

__global__ void split_x_kernel(const float* __restrict__ x, size_t total) {
    for (size_t i = (size_t)blockIdx.x * blockDim.x + threadIdx.x; i < total;
         i += (size_t)gridDim.x * blockDim.x) {
        split_bf16(x[i], g_xh[i], g_xl[i]);
    }
}

__global__ void prep_weights_kernel(const float* __restrict__ gw1, const float* __restrict__ gw2,
                                    const float* __restrict__ wih1, const float* __restrict__ whh1,
                                    const float* __restrict__ bih1, const float* __restrict__ bhh1,
                                    const float* __restrict__ wih2, const float* __restrict__ whh2,
                                    const float* __restrict__ bih2, const float* __restrict__ bhh2) {
    int idx = blockIdx.x * blockDim.x + threadIdx.x;
    if (idx < 512 * 256) {
        int n = idx >> 8;       // gate-interleaved col 4j+g
        int k = idx & 255;
        int j = n >> 2, g = n & 3;
        int orow = g * 128 + j;
        float v1, v2;
        if (k < 128) { v1 = wih1[orow * 128 + k];         v2 = wih2[orow * 128 + k]; }
        else         { v1 = whh1[orow * 128 + (k - 128)]; v2 = whh2[orow * 128 + (k - 128)]; }
        split_bf16(v1, g_B1h[idx], g_B1l[idx]);
        split_bf16(v2, g_B2h[idx], g_B2l[idx]);
    }
    if (idx < 128 * 128) {
        int n = idx >> 7, k = idx & 127;
        split_bf16(gw1[k * 128 + n], g_GW1h[idx], g_GW1l[idx]);
        split_bf16(gw2[k * 128 + n], g_GW2h[idx], g_GW2l[idx]);
    }
    if (idx < 512) {
        int j = idx >> 2, g = idx & 3;
        int orow = g * 128 + j;
        g_bias1[idx] = bih1[orow] + bhh1[orow];
        g_bias2[idx] = bih2[orow] + bhh2[orow];
    }
}

// ---------------- GCN: degree, CSR build, gather ----------------
__global__ void deg_all_kernel(const void* __restrict__ ei, int E, int N, float* __restrict__ deg) {
    long long i = (long long)blockIdx.x * blockDim.x + threadIdx.x;
    if (i >= (long long)TT * E) return;
    int t = (int)(i / E);
    int e = (int)(i - (long long)t * E);
    int d = load_idx(ei, (size_t)t * 2 * E + E + e);
    atomicAdd(&deg[(size_t)t * N + d], 1.0f);
}

// one block per t: exclusive scan of integer degree counts -> CSR offsets
__global__ void scan_offsets_kernel(const float* __restrict__ deg, int* __restrict__ offs, int N) {
    __shared__ int sm[1024];
    __shared__ int sbase;
    const int t = blockIdx.x;
    if (threadIdx.x == 0) sbase = 0;
    __syncthreads();
    const float* dt = deg + (size_t)t * N;
    int* ot = offs + (size_t)t * (N + 1);
    for (int base = 0; base < N; base += 1024) {
        int i = base + threadIdx.x;
        int v = (i < N) ? (int)dt[i] : 0;
        sm[threadIdx.x] = v;
        __syncthreads();
        for (int off = 1; off < 1024; off <<= 1) {
            int x = (threadIdx.x >= off) ? sm[threadIdx.x - off] : 0;
            __syncthreads();
            sm[threadIdx.x] += x;
            __syncthreads();
        }
        int incl = sm[threadIdx.x];
        if (i < N) ot[i] = sbase + incl - v;
        __syncthreads();
        if (threadIdx.x == 1023) sbase += sm[1023];
        __syncthreads();
    }
    if (threadIdx.x == 0) ot[N] = sbase;
}

__global__ void csr_fill_kernel(const void* __restrict__ ei, int E, int N,
                                const int* __restrict__ offs, int* __restrict__ cursor,
                                int* __restrict__ csr) {
    long long i = (long long)blockIdx.x * blockDim.x + threadIdx.x;
    if (i >= (long long)TT * E) return;
    int t = (int)(i / E);
    int e = (int)(i - (long long)t * E);
    int s = load_idx(ei, (size_t)t * 2 * E + e);
    int d = load_idx(ei, (size_t)t * 2 * E + E + e);
    int pos = atomicAdd(&cursor[(size_t)t * N + d], 1);
    csr[(size_t)t * E + offs[(size_t)t * (N + 1) + d] + pos] = s;
}

__global__ void nis_all_kernel(float* __restrict__ nis, long long total) {
    long long i = (long long)blockIdx.x * blockDim.x + threadIdx.x;
    if (i < total) nis[i] = rsqrtf(nis[i] + 1.0f);
}

// Batched (grid.y = t) CSR gather: warp handles TWO dst nodes, interleaved chains.
__global__ void gather_combine_all_kernel(const int* __restrict__ csr, const int* __restrict__ offs,
                                          const float* __restrict__ nis, const float* __restrict__ hlin,
                                          __nv_bfloat16* __restrict__ oh, __nv_bfloat16* __restrict__ ol,
                                          int N, int E) {
    const int t = blockIdx.y;
    const int* csr_t = csr + (size_t)t * E;
    const int* offs_t = offs + (size_t)t * (N + 1);
    const float* nis_t = nis + (size_t)t * N;
    const float* hlin_t = hlin + (size_t)t * N * HH;
    __nv_bfloat16* oh_t = oh + (size_t)t * N * HH;
    __nv_bfloat16* ol_t = ol + (size_t)t * N * HH;

    int w = (blockIdx.x * blockDim.x + threadIdx.x) >> 5;
    int lane = threadIdx.x & 31;
    int n0 = 2 * w;
    if (n0 >= N) return;
    int n1 = n0 + 1;
    bool has1 = (n1 < N);

    int b0 = offs_t[n0], e0 = offs_t[n0 + 1];
    int b1 = has1 ? offs_t[n1] : 0, e1 = has1 ? offs_t[n1 + 1] : 0;
    int len0 = e0 - b0, len1 = e1 - b1;
    int L = (len0 > len1) ? len0 : len1;

    float4 a0 = make_float4(0.f, 0.f, 0.f, 0.f);
    float4 a1 = make_float4(0.f, 0.f, 0.f, 0.f);
    for (int i = 0; i < L; i++) {
        if (i < len0) {
            int s = csr_t[b0 + i];
            float ns = nis_t[s];
            float4 v = ((const float4*)(hlin_t + (size_t)s * HH))[lane];
            a0.x += v.x * ns; a0.y += v.y * ns; a0.z += v.z * ns; a0.w += v.w * ns;
        }
        if (i < len1) {
            int s = csr_t[b1 + i];
            float ns = nis_t[s];
            float4 v = ((const float4*)(hlin_t + (size_t)s * HH))[lane];
            a1.x += v.x * ns; a1.y += v.y * ns; a1.z += v.z * ns; a1.w += v.w * ns;
        }
    }

    {
        float nd = nis_t[n0];
        float4 self = ((const float4*)(hlin_t + (size_t)n0 * HH))[lane];
        float4 r;
        r.x = fmaxf(nd * (a0.x + nd * self.x), 0.0f);
        r.y = fmaxf(nd * (a0.y + nd * self.y), 0.0f);
        r.z = fmaxf(nd * (a0.z + nd * self.z), 0.0f);
        r.w = fmaxf(nd * (a0.w + nd * self.w), 0.0f);
        __nv_bfloat16 h0, l0, h1, l1, h2, l2, h3, l3;
        split_bf16(r.x, h0, l0); split_bf16(r.y, h1, l1);
        split_bf16(r.z, h2, l2); split_bf16(r.w, h3, l3);
        __nv_bfloat162* dh = (__nv_bfloat162*)(oh_t + (size_t)n0 * HH + lane * 4);
        __nv_bfloat162* dl = (__nv_bfloat162*)(ol_t + (size_t)n0 * HH + lane * 4);
        dh[0] = __nv_bfloat162(h0, h1); dh[1] = __nv_bfloat162(h2, h3);
        dl[0] = __nv_bfloat162(l0, l1); dl[1] = __nv_bfloat162(l2, l3);
    }
    if (has1) {
        float nd = nis_t[n1];
        float4 self = ((const float4*)(hlin_t + (size_t)n1 * HH))[lane];
        float4 r;
        r.x = fmaxf(nd * (a1.x + nd * self.x), 0.0f);
        r.y = fmaxf(nd * (a1.y + nd * self.y), 0.0f);
        r.z = fmaxf(nd * (a1.z + nd * self.z), 0.0f);
        r.w = fmaxf(nd * (a1.w + nd * self.w), 0.0f);
        __nv_bfloat16 h0, l0, h1, l1, h2, l2, h3, l3;
        split_bf16(r.x, h0, l0); split_bf16(r.y, h1, l1);
        split_bf16(r.z, h2, l2); split_bf16(r.w, h3, l3);
        __nv_bfloat162* dh = (__nv_bfloat162*)(oh_t + (size_t)n1 * HH + lane * 4);
        __nv_bfloat162* dl = (__nv_bfloat162*)(ol_t + (size_t)n1 * HH + lane * 4);
        dh[0] = __nv_bfloat162(h0, h1); dh[1] = __nv_bfloat162(h2, h3);
        dl[0] = __nv_bfloat162(l0, l1); dl[1] = __nv_bfloat162(l2, l3);
    }
}

// ---------------- emulated-fp32 GEMM via bf16x2 (3-term) tensor mma ----------
// K chunked by 32 as TWO 16-wide sub-tiles per stage; one wait+sync per 32 K.
#define BM 128
#define BN 128
#define SUBB 16384      // one 16-wide sub-tile: Ah(4K)+Al(4K)+Bh(4K)+Bl(4K)
#define STAGE2 (2*SUBB) // 32-wide stage
#define GSMEM (3*STAGE2)

struct GemmPtrs {
    const __nv_bfloat16 *A1h, *A1l, *A2h, *A2l, *Bth, *Btl;
    const float* bias;
    float* cstate;
    float* hout;
    __nv_bfloat16 *houth, *houtl;
};

template<bool LSTM>
__device__ __forceinline__ void gemm_core(
    int M, int Nt, int K, GemmPtrs P, float* __restrict__ Cout, char* smemc) {

    const uint32_t smemBase = (uint32_t)__cvta_generic_to_shared(smemc);

    const int tid = threadIdx.x;
    const int lane = tid & 31;
    const int wid = tid >> 5;
    const int wm = wid >> 2;          // 0..1
    const int wn = wid & 3;           // 0..3
    const int row0 = blockIdx.y * BM;
    const int col0 = blockIdx.x * BN;

    float acc[4][4][4];
#pragma unroll
    for (int i = 0; i < 4; i++)
#pragma unroll
        for (int j = 0; j < 4; j++)
#pragma unroll
            for (int v = 0; v < 4; v++) acc[i][j][v] = 0.0f;

    const int CH = K / 32;

    const int lrow = tid >> 1;        // 0..127
    const int lh = tid & 1;
    const uint32_t dOff = swz((uint32_t)(lrow * 32 + lh * 16));

    auto load_chunk = [&](int ch, int buf) {
        const int gr = row0 + lrow;
        const int pa = (gr < M) ? 16 : 0;
#pragma unroll
        for (int sub = 0; sub < 2; sub++) {
            const int k0 = ch * 32 + sub * 16;
            const __nv_bfloat16 *Aph, *Apl;
            int kk;
            if (k0 < 128) { Aph = P.A1h; Apl = P.A1l; kk = k0; }
            else          { Aph = P.A2h; Apl = P.A2l; kk = k0 - 128; }
            const uint32_t base = smemBase + buf * STAGE2 + sub * SUBB;
            const size_t aoff = (size_t)gr * 128 + kk + lh * 8;
            cpasync16(base + dOff,         Aph + aoff, pa);
            cpasync16(base + 4096 + dOff,  Apl + aoff, pa);
            const size_t boff = (size_t)(col0 + lrow) * K + k0 + lh * 8;
            cpasync16(base + 8192 + dOff,  P.Bth + boff, 16);
            cpasync16(base + 12288 + dOff, P.Btl + boff, 16);
        }
    };

    const int a_r = lane & 15;
    const int a_h = lane >> 4;
    const int b_n = (lane & 7) + ((lane >> 4) << 3);
    const int b_h = (lane >> 3) & 1;

    load_chunk(0, 0);
    cp_commit();
    if (CH > 1) { load_chunk(1, 1); }
    cp_commit();

    int buf = 0;
    for (int ch = 0; ch < CH; ch++) {
        cp_wait1();
        __syncthreads();
#pragma unroll
        for (int sub = 0; sub < 2; sub++) {
            const uint32_t base = smemBase + buf * STAGE2 + sub * SUBB;
            uint32_t ah[4][4], al[4][4], bh[4][2], bl[4][2];
#pragma unroll
            for (int mf = 0; mf < 4; mf++) {
                uint32_t ao = swz((uint32_t)((wm * 64 + mf * 16 + a_r) * 32 + a_h * 16));
                ldsm4(ah[mf], base + ao);
                ldsm4(al[mf], base + 4096 + ao);
            }
#pragma unroll
            for (int nf2 = 0; nf2 < 2; nf2++) {
                uint32_t bo = swz((uint32_t)((wn * 32 + nf2 * 16 + b_n) * 32 + b_h * 16));
                uint32_t t4[4];
                ldsm4(t4, base + 8192 + bo);
                bh[2 * nf2][0] = t4[0]; bh[2 * nf2][1] = t4[1];
                bh[2 * nf2 + 1][0] = t4[2]; bh[2 * nf2 + 1][1] = t4[3];
                ldsm4(t4, base + 12288 + bo);
                bl[2 * nf2][0] = t4[0]; bl[2 * nf2][1] = t4[1];
                bl[2 * nf2 + 1][0] = t4[2]; bl[2 * nf2 + 1][1] = t4[3];
            }
#pragma unroll
            for (int mf = 0; mf < 4; mf++)
#pragma unroll
                for (int nf = 0; nf < 4; nf++)
                    mma_bf16(acc[mf][nf], ah[mf], bh[nf]);
#pragma unroll
            for (int mf = 0; mf < 4; mf++)
#pragma unroll
                for (int nf = 0; nf < 4; nf++)
                    mma_bf16(acc[mf][nf], ah[mf], bl[nf]);
#pragma unroll
            for (int mf = 0; mf < 4; mf++)
#pragma unroll
                for (int nf = 0; nf < 4; nf++)
                    mma_bf16(acc[mf][nf], al[mf], bh[nf]);
        }

        if (ch + 2 < CH) {
            int nbuf = buf + 2; if (nbuf >= 3) nbuf -= 3;
            load_chunk(ch + 2, nbuf);
        }
        cp_commit();
        if (++buf == 3) buf = 0;
    }
    __syncthreads();

    if (!LSTM) {
#pragma unroll
        for (int mf = 0; mf < 4; mf++) {
            int gr = row0 + wm * 64 + mf * 16 + (lane >> 2);
#pragma unroll
            for (int nf = 0; nf < 4; nf++) {
                int gc = col0 + wn * 32 + nf * 8 + 2 * (lane & 3);
                float b0 = P.bias[gc], b1 = P.bias[gc + 1];
                if (gr < M) {
                    float2 v = make_float2(acc[mf][nf][0] + b0, acc[mf][nf][1] + b1);
                    *(float2*)(Cout + (size_t)gr * Nt + gc) = v;
                }
                if (gr + 8 < M) {
                    float2 v = make_float2(acc[mf][nf][2] + b0, acc[mf][nf][3] + b1);
                    *(float2*)(Cout + (size_t)(gr + 8) * Nt + gc) = v;
                }
            }
        }
    } else {
        float (*sC)[132] = (float (*)[132])smemc;
        const int j0 = col0 >> 2;
        for (int ch2 = 0; ch2 < 2; ch2++) {
            __syncthreads();
            if (wm == ch2) {
#pragma unroll
                for (int mf = 0; mf < 4; mf++) {
                    int rl = mf * 16 + (lane >> 2);
#pragma unroll
                    for (int nf = 0; nf < 4; nf++) {
                        int cl = wn * 32 + nf * 8 + 2 * (lane & 3);
                        float b0 = P.bias[col0 + cl], b1 = P.bias[col0 + cl + 1];
                        sC[rl][cl] = acc[mf][nf][0] + b0;
                        sC[rl][cl + 1] = acc[mf][nf][1] + b1;
                        sC[rl + 8][cl] = acc[mf][nf][2] + b0;
                        sC[rl + 8][cl + 1] = acc[mf][nf][3] + b1;
                    }
                }
            }
            __syncthreads();
            for (int q = tid; q < 64 * 32; q += 256) {
                int rl = q >> 5, jl = q & 31;
                int node = row0 + ch2 * 64 + rl;
                if (node < M) {
                    float4 g4 = *(float4*)&sC[rl][4 * jl];
                    size_t ci = (size_t)node * HH + j0 + jl;
                    float cn = sigm(g4.y) * P.cstate[ci] + sigm(g4.x) * tanhf(g4.z);
                    P.cstate[ci] = cn;
                    float hv = sigm(g4.w) * tanhf(cn);
                    if (P.hout) P.hout[ci] = hv;
                    split_bf16(hv, P.houth[ci], P.houtl[ci]);
                }
            }
        }
    }
}

// out_proj body (shared): warp computes out[n] = h2 . w + b for grid-stride nodes
__device__ __forceinline__ void out_proj_body(
    const __nv_bfloat16* __restrict__ h2h, const __nv_bfloat16* __restrict__ h2l,
    const float* __restrict__ w, const float* __restrict__ b,
    float* __restrict__ out, int n, int warpId, int nWarps, int lane) {
    float4 wv = ((const float4*)w)[lane];
    float bv = b[0];
    for (int node = warpId; node < n; node += nWarps) {
        const __nv_bfloat162* ph = (const __nv_bfloat162*)(h2h + (size_t)node * HH + lane * 4);
        const __nv_bfloat162* pl = (const __nv_bfloat162*)(h2l + (size_t)node * HH + lane * 4);
        __nv_bfloat162 hh0 = ph[0], hh1 = ph[1], ll0 = pl[0], ll1 = pl[1];
        float v0 = __bfloat162float(hh0.x) + __bfloat162float(ll0.x);
        float v1 = __bfloat162float(hh0.y) + __bfloat162float(ll0.y);
        float v2 = __bfloat162float(hh1.x) + __bfloat162float(ll1.x);
        float v3 = __bfloat162float(hh1.y) + __bfloat162float(ll1.y);
        float s = v0 * wv.x + v1 * wv.y + v2 * wv.z + v3 * wv.w;
#pragma unroll
        for (int off = 16; off; off >>= 1) s += __shfl_xor_sync(0xFFFFFFFFu, s, off);
        if (lane == 0) out[node] = s + bv;
    }
}

template<bool LSTM>
__global__ void __launch_bounds__(256) mma_gemm_kernel(
    int M, int Nt, int K, GemmPtrs P, float* Cout) {
    extern __shared__ char smemc[];
    gemm_core<LSTM>(M, Nt, K, P, Cout, smemc);
}

// merged launch: z < nGemm -> GEMM slice (z==0 -> PA, z==1 -> PB);
// z == nGemm -> out_proj of the PREVIOUS timestep (planes already final).
__global__ void __launch_bounds__(256) lstm_pair_kernel(
    int M, int nGemm, GemmPtrs PA, GemmPtrs PB,
    const __nv_bfloat16* oph, const __nv_bfloat16* opl,
    const float* ow, const float* ob, float* ovec) {
    extern __shared__ char smemc[];
    if ((int)blockIdx.z >= nGemm) {
        const int bid = blockIdx.y * gridDim.x + blockIdx.x;
        const int warpId = bid * (blockDim.x >> 5) + (threadIdx.x >> 5);
        const int nWarps = gridDim.x * gridDim.y * (blockDim.x >> 5);
        out_proj_body(oph, opl, ow, ob, ovec, M, warpId, nWarps, threadIdx.x & 31);
        return;
    }
    gemm_core<true>(M, G4, 256, blockIdx.z ? PB : PA, nullptr, smemc);
}

// standalone out_proj (final timestep)
__global__ void out_proj_kernel(const __nv_bfloat16* __restrict__ h2h,
                                const __nv_bfloat16* __restrict__ h2l,
                                const float* __restrict__ w,
                                const float* __restrict__ b, float* __restrict__ out, int n) {
    int warpId = (blockIdx.x * blockDim.x + threadIdx.x) >> 5;
    int nWarps = (gridDim.x * blockDim.x) >> 5;
    out_proj_body(h2h, h2l, w, b, out, n, warpId, nWarps, threadIdx.x & 31);
}

__global__ void copy_states_kernel(const float* __restrict__ st, float* __restrict__ out, size_t nh) {
    size_t i = (size_t)blockIdx.x * blockDim.x + threadIdx.x;
    size_t total = 4 * nh;
    for (; i < total; i += (size_t)gridDim.x * blockDim.x) out[i] = st[i];
}

// ---------------- host launch ----------------
static inline int cdiv(int a, int b) { return (a + b - 1) / b; }
#define SYM(var, sym) cudaGetSymbolAddress((void**)&var, sym)

extern "C" void kernel_launch(void* const* d_in, const int* in_sizes, int n_in,
                              void* d_out, int out_size) {
    const float* x    = (const float*)d_in[0];
    const void*  ei   = d_in[1];
    const float* gw1  = (const float*)d_in[2];
    const float* gb1  = (const float*)d_in[3];
    const float* gw2  = (const float*)d_in[4];
    const float* gb2  = (const float*)d_in[5];
    const float* wih1 = (const float*)d_in[6];
    const float* whh1 = (const float*)d_in[7];
    const float* bih1 = (const float*)d_in[8];
    const float* bhh1 = (const float*)d_in[9];
    const float* wih2 = (const float*)d_in[10];
    const float* whh2 = (const float*)d_in[11];
    const float* bih2 = (const float*)d_in[12];
    const float* bhh2 = (const float*)d_in[13];
    const float* outw = (const float*)d_in[14];
    const float* outb = (const float*)d_in[15];

    const int N = in_sizes[0] / (TT * FIN);
    const int E = in_sizes[1] / (2 * TT);
    float* out = (float*)d_out;

    __nv_bfloat16 *xh, *xl, *fh, *fl, *b2h, *b2l;
    __nv_bfloat16 *h1h_a, *h1l_a, *h1h_b, *h1l_b, *h2h_a, *h2l_a, *h2h_b, *h2l_b;
    __nv_bfloat16 *B1h, *B1l, *B2h, *B2l, *GW1h, *GW1l, *GW2h, *GW2l;
    float *nis, *hlin, *state, *bias1, *bias2;
    int *offs, *cursor, *csr;
    SYM(xh, g_xh); SYM(xl, g_xl); SYM(fh, g_fh); SYM(fl, g_fl);
    SYM(b2h, g_b2h); SYM(b2l, g_b2l);
    SYM(h1h_a, g_h1h_a); SYM(h1l_a, g_h1l_a); SYM(h1h_b, g_h1h_b); SYM(h1l_b, g_h1l_b);
    SYM(h2h_a, g_h2h_a); SYM(h2l_a, g_h2l_a); SYM(h2h_b, g_h2h_b); SYM(h2l_b, g_h2l_b);
    SYM(B1h, g_B1h); SYM(B1l, g_B1l); SYM(B2h, g_B2h); SYM(B2l, g_B2l);
    SYM(GW1h, g_GW1h); SYM(GW1l, g_GW1l); SYM(GW2h, g_GW2h); SYM(GW2l, g_GW2l);
    SYM(nis, g_nis); SYM(hlin, g_hlin);
    SYM(offs, g_offs); SYM(cursor, g_cursor); SYM(csr, g_csr);
    SYM(state, g_state); SYM(bias1, g_bias1); SYM(bias2, g_bias2);

    const size_t NH = (size_t)N * HH;
    const long long TN = (long long)TT * N;

    const int mbA = (int)((TN + BM - 1) / BM);  // 3125
    const int mbL = cdiv(N, BM);                // 391
    const int gx = cdiv(cdiv(N, 2) * 32, 256);  // gather grid.x (2 nodes/warp)

    cudaFuncSetAttribute(mma_gemm_kernel<false>, cudaFuncAttributeMaxDynamicSharedMemorySize, GSMEM);
    cudaFuncSetAttribute(mma_gemm_kernel<true>,  cudaFuncAttributeMaxDynamicSharedMemorySize, GSMEM);
    cudaFuncSetAttribute(lstm_pair_kernel,       cudaFuncAttributeMaxDynamicSharedMemorySize, GSMEM);

    GemmPtrs P{};

    // launch order keeps GCN L1 GEMM at #5 (ncu sentinel across rounds)
    detect_idx_kernel<<<1, 1>>>(ei);                                            // 1
    prep_weights_kernel<<<cdiv(512 * 256, 256), 256>>>(gw1, gw2, wih1, whh1,    // 2
                                                       bih1, bhh1, wih2, whh2, bih2, bhh2);
    split_x_kernel<<<2048, 256>>>(x, (size_t)TN * FIN);                         // 3
    cudaMemsetAsync(nis, 0, TN * sizeof(float));                                // 4

    // -------- GCN layer 1 GEMM (batched over all t) --------                  // 5
    P = GemmPtrs{xh, xl, nullptr, nullptr, GW1h, GW1l, gb1, nullptr, nullptr, nullptr, nullptr};
    mma_gemm_kernel<false><<<dim3(1, mbA), 256, GSMEM>>>((int)TN, HH, 128, P, hlin);

    // -------- degrees -> CSR offsets -> fill -> nis --------
    deg_all_kernel<<<(unsigned)(((long long)TT * E + 255) / 256), 256>>>(ei, E, N, nis);
    scan_offsets_kernel<<<TT, 1024>>>(nis, offs, N);
    cudaMemsetAsync(cursor, 0, (size_t)TT * N * sizeof(int));
    csr_fill_kernel<<<(unsigned)(((long long)TT * E + 255) / 256), 256>>>(ei, E, N, offs, cursor, csr);
    nis_all_kernel<<<(unsigned)((TN + 255) / 256), 256>>>(nis, TN);

    // -------- GCN layer 1 gather (batched over t, 2 nodes/warp) --------
    gather_combine_all_kernel<<<dim3(gx, TT), 256>>>(csr, offs, nis, hlin, b2h, b2l, N, E);

    // -------- GCN layer 2 --------
    P = GemmPtrs{b2h, b2l, nullptr, nullptr, GW2h, GW2l, gb2, nullptr, nullptr, nullptr, nullptr};
    mma_gemm_kernel<false><<<dim3(1, mbA), 256, GSMEM>>>((int)TN, HH, 128, P, hlin);
    gather_combine_all_kernel<<<dim3(gx, TT), 256>>>(csr, offs, nis, hlin, fh, fl, N, E);

    // -------- LSTM over time (merged pairs + folded out_proj slices) --------
    cudaMemsetAsync(state, 0, 4 * NH * sizeof(float));
    cudaMemsetAsync(h1h_a, 0, NH * sizeof(__nv_bfloat16));
    cudaMemsetAsync(h1l_a, 0, NH * sizeof(__nv_bfloat16));
    cudaMemsetAsync(h2h_a, 0, NH * sizeof(__nv_bfloat16));
    cudaMemsetAsync(h2l_a, 0, NH * sizeof(__nv_bfloat16));

    float* h1a = state;               // final h1 (t=7 odd writes A bufs)
    float* c1  = state + NH;
    float* h2a = state + 2 * NH;
    float* c2  = state + 3 * NH;

    auto L1ptrs = [&](int t) -> GemmPtrs {
        const int odd = t & 1;
        return GemmPtrs{
            fh + (size_t)t * NH, fl + (size_t)t * NH,
            odd ? h1h_b : h1h_a, odd ? h1l_b : h1l_a,   // h1_{t-1} in
            B1h, B1l, bias1, c1,
            (t == TT - 1) ? h1a : nullptr,
            odd ? h1h_a : h1h_b, odd ? h1l_a : h1l_b};  // h1_t out
    };
    auto L2ptrs = [&](int t) -> GemmPtrs {
        const int odd = t & 1;
        return GemmPtrs{
            odd ? h1h_a : h1h_b, odd ? h1l_a : h1l_b,   // h1_t in
            odd ? h2h_b : h2h_a, odd ? h2l_b : h2l_a,   // h2_{t-1} in
            B2h, B2l, bias2, c2,
            (t == TT - 1) ? h2a : nullptr,
            odd ? h2h_a : h2h_b, odd ? h2l_a : h2l_b};  // h2_t out
    };
    auto h2h_of = [&](int t) { return (t & 1) ? h2h_a : h2h_b; };
    auto h2l_of = [&](int t) { return (t & 1) ? h2l_a : h2l_b; };

    // t=0 layer 1
    mma_gemm_kernel<true><<<dim3(4, mbL), 256, GSMEM>>>(N, G4, 256, L1ptrs(0), nullptr);
    for (int t = 0; t < TT; t++) {
        const bool hasOp = (t >= 1);   // out_proj(t-1) rides along
        const __nv_bfloat16* oph = hasOp ? h2h_of(t - 1) : nullptr;
        const __nv_bfloat16* opl = hasOp ? h2l_of(t - 1) : nullptr;
        float* ovec = hasOp ? out + (size_t)(t - 1) * N : nullptr;
        if (t + 1 < TT) {
            // z0: layer2(t), z1: layer1(t+1), z2 (if hasOp): out_proj(t-1)
            lstm_pair_kernel<<<dim3(4, mbL, hasOp ? 3 : 2), 256, GSMEM>>>(
                N, 2, L2ptrs(t), L1ptrs(t + 1), oph, opl, outw, outb, ovec);
        } else {
            // final: z0: layer2(7), z1: out_proj(6)
            lstm_pair_kernel<<<dim3(4, mbL, 2), 256, GSMEM>>>(
                N, 1, L2ptrs(t), L2ptrs(t), oph, opl, outw, outb, ovec);
        }
    }
    // out_proj(7)
    out_proj_kernel<<<cdiv(N * 32, 256), 256>>>(h2h_of(TT - 1), h2l_of(TT - 1),
                                                outw, outb, out + (size_t)(TT - 1) * N, N);

    // -------- tail: h1, c1, h2, c2 (t=7 odd -> finals in buf A = state) ------
    copy_states_kernel<<<1024, 256>>>(state, out + (size_t)TT * N, NH);
}

// round 17
// speedup vs baseline: 1.1822x; 1.0124x over previous
#include <cuda_runtime.h>
#include <cuda_bf16.h>
#include <math.h>
#include <stdint.h>

#define TT 8
#define FIN 128
#define HH 128
#define NMAX 50048
#define EMAX 800000
#define G4 (4*HH)

// ---------------- device scratch (allocation-free rule: __device__ globals) ----
static __device__ __nv_bfloat16 g_xh[(size_t)TT * NMAX * HH];
static __device__ __nv_bfloat16 g_xl[(size_t)TT * NMAX * HH];
static __device__ __nv_bfloat16 g_fh[(size_t)TT * NMAX * HH];   // feats hi
static __device__ __nv_bfloat16 g_fl[(size_t)TT * NMAX * HH];   // feats lo
static __device__ __nv_bfloat16 g_b2h[(size_t)TT * NMAX * HH];  // gcn layer1 out hi
static __device__ __nv_bfloat16 g_b2l[(size_t)TT * NMAX * HH];
static __device__ float g_nis[(size_t)TT * NMAX];               // deg then deg^{-1/2}
static __device__ float g_hlin[(size_t)TT * NMAX * HH];         // batched x@W+b
static __device__ int   g_offs[(size_t)TT * (NMAX + 1)];        // CSR row offsets
static __device__ int   g_cursor[(size_t)TT * NMAX];            // fill cursors
static __device__ int   g_csr[(size_t)TT * EMAX];               // src ids grouped by dst
static __device__ float g_state[(size_t)4 * NMAX * HH];         // h1a,c1,h2a,c2
static __device__ __nv_bfloat16 g_h1h_a[(size_t)NMAX * HH];
static __device__ __nv_bfloat16 g_h1l_a[(size_t)NMAX * HH];
static __device__ __nv_bfloat16 g_h1h_b[(size_t)NMAX * HH];
static __device__ __nv_bfloat16 g_h1l_b[(size_t)NMAX * HH];
static __device__ __nv_bfloat16 g_h2h_a[(size_t)NMAX * HH];
static __device__ __nv_bfloat16 g_h2l_a[(size_t)NMAX * HH];
static __device__ __nv_bfloat16 g_h2h_b[(size_t)NMAX * HH];
static __device__ __nv_bfloat16 g_h2l_b[(size_t)NMAX * HH];
// LSTM weights, gate-interleaved cols [n'=4j+g][k], K-major, K=256 = [Wih ; Whh]
static __device__ __nv_bfloat16 g_B1h[512 * 256];
static __device__ __nv_bfloat16 g_B1l[512 * 256];
static __device__ __nv_bfloat16 g_B2h[512 * 256];
static __device__ __nv_bfloat16 g_B2l[512 * 256];
static __device__ __nv_bfloat16 g_GW1h[128 * 128];              // gcn W^T [n][k]
static __device__ __nv_bfloat16 g_GW1l[128 * 128];
static __device__ __nv_bfloat16 g_GW2h[128 * 128];
static __device__ __nv_bfloat16 g_GW2l[128 * 128];
static __device__ float g_bias1[G4];
static __device__ float g_bias2[G4];
static __device__ int   g_idx64;

// ---------------- helpers ----------------
__device__ __forceinline__ int load_idx(const void* p, size_t off) {
    return g_idx64 ? (int)((const long long*)p)[off] : ((const int*)p)[off];
}
__device__ __forceinline__ float sigm(float x) { return 1.0f / (1.0f + expf(-x)); }

__device__ __forceinline__ void split_bf16(float v, __nv_bfloat16& h, __nv_bfloat16& l) {
    h = __float2bfloat16(v);
    l = __float2bfloat16(v - __bfloat162float(h));
}

__device__ __forceinline__ void cpasync16(uint32_t dst, const void* src, int sz) {
    asm volatile("cp.async.cg.shared.global [%0], [%1], 16, %2;\n" :: "r"(dst), "l"(src), "r"(sz));
}
__device__ __forceinline__ void cp_commit() { asm volatile("cp.async.commit_group;\n"); }
__device__ __forceinline__ void cp_wait1() { asm volatile("cp.async.wait_group 1;\n"); }

__device__ __forceinline__ uint32_t swz(uint32_t o) { return o ^ ((o >> 3) & 0x10); }

__device__ __forceinline__ void ldsm4(uint32_t* r, uint32_t addr) {
    asm volatile("ldmatrix.sync.aligned.m8n8.x4.shared.b16 {%0,%1,%2,%3}, [%4];"
                 : "=r"(r[0]), "=r"(r[1]), "=r"(r[2]), "=r"(r[3]) : "r"(addr));
}

__device__ __forceinline__ void mma_bf16(float* d, const uint32_t* a, const uint32_t* b) {
    asm volatile(
        "mma.sync.aligned.m16n8k16.row.col.f32.bf16.bf16.f32 "
        "{%0,%1,%2,%3}, {%4,%5,%6,%7}, {%8,%9}, {%0,%1,%2,%3};\n"
        : "+f"(d[0]), "+f"(d[1]), "+f"(d[2]), "+f"(d[3])
        : "r"(a[0]), "r"(a[1]), "r"(a[2]), "r"(a[3]), "r"(b[0]), "r"(b[1]));
}

// ---------------- prep kernels ----------------
__global__ void detect_idx_kernel(const void* ei) {
    const int* p = (const int*)ei;
    int s = 0;
    for (int i = 1; i < 257; i += 2) s |= p[i];
    g_idx64 = (s == 0) ? 1 : 0;
}

__global__ void split_x_kernel(const float* __restrict__ x, size_t total) {
    for (size_t i = (size_t)blockIdx.x * blockDim.x + threadIdx.x; i < total;
         i += (size_t)gridDim.x * blockDim.x) {
        split_bf16(x[i], g_xh[i], g_xl[i]);
    }
}

__global__ void prep_weights_kernel(const float* __restrict__ gw1, const float* __restrict__ gw2,
                                    const float* __restrict__ wih1, const float* __restrict__ whh1,
                                    const float* __restrict__ bih1, const float* __restrict__ bhh1,
                                    const float* __restrict__ wih2, const float* __restrict__ whh2,
                                    const float* __restrict__ bih2, const float* __restrict__ bhh2) {
    int idx = blockIdx.x * blockDim.x + threadIdx.x;
    if (idx < 512 * 256) {
        int n = idx >> 8;       // gate-interleaved col 4j+g
        int k = idx & 255;
        int j = n >> 2, g = n & 3;
        int orow = g * 128 + j;
        float v1, v2;
        if (k < 128) { v1 = wih1[orow * 128 + k];         v2 = wih2[orow * 128 + k]; }
        else         { v1 = whh1[orow * 128 + (k - 128)]; v2 = whh2[orow * 128 + (k - 128)]; }
        split_bf16(v1, g_B1h[idx], g_B1l[idx]);
        split_bf16(v2, g_B2h[idx], g_B2l[idx]);
    }
    if (idx < 128 * 128) {
        int n = idx >> 7, k = idx & 127;
        split_bf16(gw1[k * 128 + n], g_GW1h[idx], g_GW1l[idx]);
        split_bf16(gw2[k * 128 + n], g_GW2h[idx], g_GW2l[idx]);
    }
    if (idx < 512) {
        int j = idx >> 2, g = idx & 3;
        int orow = g * 128 + j;
        g_bias1[idx] = bih1[orow] + bhh1[orow];
        g_bias2[idx] = bih2[orow] + bhh2[orow];
    }
}

// ---------------- GCN: degree, CSR build, gather ----------------
__global__ void deg_all_kernel(const void* __restrict__ ei, int E, int N, float* __restrict__ deg) {
    long long i = (long long)blockIdx.x * blockDim.x + threadIdx.x;
    if (i >= (long long)TT * E) return;
    int t = (int)(i / E);
    int e = (int)(i - (long long)t * E);
    int d = load_idx(ei, (size_t)t * 2 * E + E + e);
    atomicAdd(&deg[(size_t)t * N + d], 1.0f);
}

// one block per t: exclusive scan of integer degree counts -> CSR offsets
__global__ void scan_offsets_kernel(const float* __restrict__ deg, int* __restrict__ offs, int N) {
    __shared__ int sm[1024];
    __shared__ int sbase;
    const int t = blockIdx.x;
    if (threadIdx.x == 0) sbase = 0;
    __syncthreads();
    const float* dt = deg + (size_t)t * N;
    int* ot = offs + (size_t)t * (N + 1);
    for (int base = 0; base < N; base += 1024) {
        int i = base + threadIdx.x;
        int v = (i < N) ? (int)dt[i] : 0;
        sm[threadIdx.x] = v;
        __syncthreads();
        for (int off = 1; off < 1024; off <<= 1) {
            int x = (threadIdx.x >= off) ? sm[threadIdx.x - off] : 0;
            __syncthreads();
            sm[threadIdx.x] += x;
            __syncthreads();
        }
        int incl = sm[threadIdx.x];
        if (i < N) ot[i] = sbase + incl - v;
        __syncthreads();
        if (threadIdx.x == 1023) sbase += sm[1023];
        __syncthreads();
    }
    if (threadIdx.x == 0) ot[N] = sbase;
}

__global__ void csr_fill_kernel(const void* __restrict__ ei, int E, int N,
                                const int* __restrict__ offs, int* __restrict__ cursor,
                                int* __restrict__ csr) {
    long long i = (long long)blockIdx.x * blockDim.x + threadIdx.x;
    if (i >= (long long)TT * E) return;
    int t = (int)(i / E);
    int e = (int)(i - (long long)t * E);
    int s = load_idx(ei, (size_t)t * 2 * E + e);
    int d = load_idx(ei, (size_t)t * 2 * E + E + e);
    int pos = atomicAdd(&cursor[(size_t)t * N + d], 1);
    csr[(size_t)t * E + offs[(size_t)t * (N + 1) + d] + pos] = s;
}

__global__ void nis_all_kernel(float* __restrict__ nis, long long total) {
    long long i = (long long)blockIdx.x * blockDim.x + threadIdx.x;
    if (i < total) nis[i] = rsqrtf(nis[i] + 1.0f);
}

// Batched (grid.y = t) CSR gather: warp handles TWO dst nodes, interleaved chains.
__global__ void gather_combine_all_kernel(const int* __restrict__ csr, const int* __restrict__ offs,
                                          const float* __restrict__ nis, const float* __restrict__ hlin,
                                          __nv_bfloat16* __restrict__ oh, __nv_bfloat16* __restrict__ ol,
                                          int N, int E) {
    const int t = blockIdx.y;
    const int* csr_t = csr + (size_t)t * E;
    const int* offs_t = offs + (size_t)t * (N + 1);
    const float* nis_t = nis + (size_t)t * N;
    const float* hlin_t = hlin + (size_t)t * N * HH;
    __nv_bfloat16* oh_t = oh + (size_t)t * N * HH;
    __nv_bfloat16* ol_t = ol + (size_t)t * N * HH;

    int w = (blockIdx.x * blockDim.x + threadIdx.x) >> 5;
    int lane = threadIdx.x & 31;
    int n0 = 2 * w;
    if (n0 >= N) return;
    int n1 = n0 + 1;
    bool has1 = (n1 < N);

    int b0 = offs_t[n0], e0 = offs_t[n0 + 1];
    int b1 = has1 ? offs_t[n1] : 0, e1 = has1 ? offs_t[n1 + 1] : 0;
    int len0 = e0 - b0, len1 = e1 - b1;
    int L = (len0 > len1) ? len0 : len1;

    float4 a0 = make_float4(0.f, 0.f, 0.f, 0.f);
    float4 a1 = make_float4(0.f, 0.f, 0.f, 0.f);
    for (int i = 0; i < L; i++) {
        if (i < len0) {
            int s = csr_t[b0 + i];
            float ns = nis_t[s];
            float4 v = ((const float4*)(hlin_t + (size_t)s * HH))[lane];
            a0.x += v.x * ns; a0.y += v.y * ns; a0.z += v.z * ns; a0.w += v.w * ns;
        }
        if (i < len1) {
            int s = csr_t[b1 + i];
            float ns = nis_t[s];
            float4 v = ((const float4*)(hlin_t + (size_t)s * HH))[lane];
            a1.x += v.x * ns; a1.y += v.y * ns; a1.z += v.z * ns; a1.w += v.w * ns;
        }
    }

    {
        float nd = nis_t[n0];
        float4 self = ((const float4*)(hlin_t + (size_t)n0 * HH))[lane];
        float4 r;
        r.x = fmaxf(nd * (a0.x + nd * self.x), 0.0f);
        r.y = fmaxf(nd * (a0.y + nd * self.y), 0.0f);
        r.z = fmaxf(nd * (a0.z + nd * self.z), 0.0f);
        r.w = fmaxf(nd * (a0.w + nd * self.w), 0.0f);
        __nv_bfloat16 h0, l0, h1, l1, h2, l2, h3, l3;
        split_bf16(r.x, h0, l0); split_bf16(r.y, h1, l1);
        split_bf16(r.z, h2, l2); split_bf16(r.w, h3, l3);
        __nv_bfloat162* dh = (__nv_bfloat162*)(oh_t + (size_t)n0 * HH + lane * 4);
        __nv_bfloat162* dl = (__nv_bfloat162*)(ol_t + (size_t)n0 * HH + lane * 4);
        dh[0] = __nv_bfloat162(h0, h1); dh[1] = __nv_bfloat162(h2, h3);
        dl[0] = __nv_bfloat162(l0, l1); dl[1] = __nv_bfloat162(l2, l3);
    }
    if (has1) {
        float nd = nis_t[n1];
        float4 self = ((const float4*)(hlin_t + (size_t)n1 * HH))[lane];
        float4 r;
        r.x = fmaxf(nd * (a1.x + nd * self.x), 0.0f);
        r.y = fmaxf(nd * (a1.y + nd * self.y), 0.0f);
        r.z = fmaxf(nd * (a1.z + nd * self.z), 0.0f);
        r.w = fmaxf(nd * (a1.w + nd * self.w), 0.0f);
        __nv_bfloat16 h0, l0, h1, l1, h2, l2, h3, l3;
        split_bf16(r.x, h0, l0); split_bf16(r.y, h1, l1);
        split_bf16(r.z, h2, l2); split_bf16(r.w, h3, l3);
        __nv_bfloat162* dh = (__nv_bfloat162*)(oh_t + (size_t)n1 * HH + lane * 4);
        __nv_bfloat162* dl = (__nv_bfloat162*)(ol_t + (size_t)n1 * HH + lane * 4);
        dh[0] = __nv_bfloat162(h0, h1); dh[1] = __nv_bfloat162(h2, h3);
        dl[0] = __nv_bfloat162(l0, l1); dl[1] = __nv_bfloat162(l2, l3);
    }
}

// ---------------- emulated-fp32 GEMM via bf16x2 (3-term) tensor mma ----------
// K chunked by 32 as TWO 16-wide sub-tiles per stage; one wait+sync per 32 K.
// LSTM epilogue: single full-tile smem stage (128x132 fp32 fits the 96KB
// dynamic smem) -> 2 post-mainloop syncs instead of 5.
#define BM 128
#define BN 128
#define SUBB 16384      // one 16-wide sub-tile: Ah(4K)+Al(4K)+Bh(4K)+Bl(4K)
#define STAGE2 (2*SUBB) // 32-wide stage
#define GSMEM (3*STAGE2)

struct GemmPtrs {
    const __nv_bfloat16 *A1h, *A1l, *A2h, *A2l, *Bth, *Btl;
    const float* bias;
    float* cstate;
    float* hout;
    __nv_bfloat16 *houth, *houtl;
};

template<bool LSTM>
__device__ __forceinline__ void gemm_core(
    int M, int Nt, int K, GemmPtrs P, float* __restrict__ Cout, char* smemc) {

    const uint32_t smemBase = (uint32_t)__cvta_generic_to_shared(smemc);

    const int tid = threadIdx.x;
    const int lane = tid & 31;
    const int wid = tid >> 5;
    const int wm = wid >> 2;          // 0..1
    const int wn = wid & 3;           // 0..3
    const int row0 = blockIdx.y * BM;
    const int col0 = blockIdx.x * BN;

    float acc[4][4][4];
#pragma unroll
    for (int i = 0; i < 4; i++)
#pragma unroll
        for (int j = 0; j < 4; j++)
#pragma unroll
            for (int v = 0; v < 4; v++) acc[i][j][v] = 0.0f;

    const int CH = K / 32;

    const int lrow = tid >> 1;        // 0..127
    const int lh = tid & 1;
    const uint32_t dOff = swz((uint32_t)(lrow * 32 + lh * 16));

    auto load_chunk = [&](int ch, int buf) {
        const int gr = row0 + lrow;
        const int pa = (gr < M) ? 16 : 0;
#pragma unroll
        for (int sub = 0; sub < 2; sub++) {
            const int k0 = ch * 32 + sub * 16;
            const __nv_bfloat16 *Aph, *Apl;
            int kk;
            if (k0 < 128) { Aph = P.A1h; Apl = P.A1l; kk = k0; }
            else          { Aph = P.A2h; Apl = P.A2l; kk = k0 - 128; }
            const uint32_t base = smemBase + buf * STAGE2 + sub * SUBB;
            const size_t aoff = (size_t)gr * 128 + kk + lh * 8;
            cpasync16(base + dOff,         Aph + aoff, pa);
            cpasync16(base + 4096 + dOff,  Apl + aoff, pa);
            const size_t boff = (size_t)(col0 + lrow) * K + k0 + lh * 8;
            cpasync16(base + 8192 + dOff,  P.Bth + boff, 16);
            cpasync16(base + 12288 + dOff, P.Btl + boff, 16);
        }
    };

    const int a_r = lane & 15;
    const int a_h = lane >> 4;
    const int b_n = (lane & 7) + ((lane >> 4) << 3);
    const int b_h = (lane >> 3) & 1;

    load_chunk(0, 0);
    cp_commit();
    if (CH > 1) { load_chunk(1, 1); }
    cp_commit();

    int buf = 0;
    for (int ch = 0; ch < CH; ch++) {
        cp_wait1();
        __syncthreads();
#pragma unroll
        for (int sub = 0; sub < 2; sub++) {
            const uint32_t base = smemBase + buf * STAGE2 + sub * SUBB;
            uint32_t ah[4][4], al[4][4], bh[4][2], bl[4][2];
#pragma unroll
            for (int mf = 0; mf < 4; mf++) {
                uint32_t ao = swz((uint32_t)((wm * 64 + mf * 16 + a_r) * 32 + a_h * 16));
                ldsm4(ah[mf], base + ao);
                ldsm4(al[mf], base + 4096 + ao);
            }
#pragma unroll
            for (int nf2 = 0; nf2 < 2; nf2++) {
                uint32_t bo = swz((uint32_t)((wn * 32 + nf2 * 16 + b_n) * 32 + b_h * 16));
                uint32_t t4[4];
                ldsm4(t4, base + 8192 + bo);
                bh[2 * nf2][0] = t4[0]; bh[2 * nf2][1] = t4[1];
                bh[2 * nf2 + 1][0] = t4[2]; bh[2 * nf2 + 1][1] = t4[3];
                ldsm4(t4, base + 12288 + bo);
                bl[2 * nf2][0] = t4[0]; bl[2 * nf2][1] = t4[1];
                bl[2 * nf2 + 1][0] = t4[2]; bl[2 * nf2 + 1][1] = t4[3];
            }
#pragma unroll
            for (int mf = 0; mf < 4; mf++)
#pragma unroll
                for (int nf = 0; nf < 4; nf++)
                    mma_bf16(acc[mf][nf], ah[mf], bh[nf]);
#pragma unroll
            for (int mf = 0; mf < 4; mf++)
#pragma unroll
                for (int nf = 0; nf < 4; nf++)
                    mma_bf16(acc[mf][nf], ah[mf], bl[nf]);
#pragma unroll
            for (int mf = 0; mf < 4; mf++)
#pragma unroll
                for (int nf = 0; nf < 4; nf++)
                    mma_bf16(acc[mf][nf], al[mf], bh[nf]);
        }

        if (ch + 2 < CH) {
            int nbuf = buf + 2; if (nbuf >= 3) nbuf -= 3;
            load_chunk(ch + 2, nbuf);
        }
        cp_commit();
        if (++buf == 3) buf = 0;
    }
    __syncthreads();

    if (!LSTM) {
#pragma unroll
        for (int mf = 0; mf < 4; mf++) {
            int gr = row0 + wm * 64 + mf * 16 + (lane >> 2);
#pragma unroll
            for (int nf = 0; nf < 4; nf++) {
                int gc = col0 + wn * 32 + nf * 8 + 2 * (lane & 3);
                float b0 = P.bias[gc], b1 = P.bias[gc + 1];
                if (gr < M) {
                    float2 v = make_float2(acc[mf][nf][0] + b0, acc[mf][nf][1] + b1);
                    *(float2*)(Cout + (size_t)gr * Nt + gc) = v;
                }
                if (gr + 8 < M) {
                    float2 v = make_float2(acc[mf][nf][2] + b0, acc[mf][nf][3] + b1);
                    *(float2*)(Cout + (size_t)(gr + 8) * Nt + gc) = v;
                }
            }
        }
    } else {
        // single full-tile stage: wm=0 rows 0..63, wm=1 rows 64..127 concurrently
        float (*sC)[132] = (float (*)[132])smemc;
        const int j0 = col0 >> 2;
#pragma unroll
        for (int mf = 0; mf < 4; mf++) {
            int rl = wm * 64 + mf * 16 + (lane >> 2);
#pragma unroll
            for (int nf = 0; nf < 4; nf++) {
                int cl = wn * 32 + nf * 8 + 2 * (lane & 3);
                float b0 = P.bias[col0 + cl], b1 = P.bias[col0 + cl + 1];
                sC[rl][cl] = acc[mf][nf][0] + b0;
                sC[rl][cl + 1] = acc[mf][nf][1] + b1;
                sC[rl + 8][cl] = acc[mf][nf][2] + b0;
                sC[rl + 8][cl + 1] = acc[mf][nf][3] + b1;
            }
        }
        __syncthreads();
        for (int q = tid; q < 128 * 32; q += 256) {
            int rl = q >> 5, jl = q & 31;
            int node = row0 + rl;
            if (node < M) {
                float4 g4 = *(float4*)&sC[rl][4 * jl];
                size_t ci = (size_t)node * HH + j0 + jl;
                float cn = sigm(g4.y) * P.cstate[ci] + sigm(g4.x) * tanhf(g4.z);
                P.cstate[ci] = cn;
                float hv = sigm(g4.w) * tanhf(cn);
                if (P.hout) P.hout[ci] = hv;
                split_bf16(hv, P.houth[ci], P.houtl[ci]);
            }
        }
    }
}

// out_proj body (shared): warp computes out[n] = h2 . w + b for grid-stride nodes
__device__ __forceinline__ void out_proj_body(
    const __nv_bfloat16* __restrict__ h2h, const __nv_bfloat16* __restrict__ h2l,
    const float* __restrict__ w, const float* __restrict__ b,
    float* __restrict__ out, int n, int warpId, int nWarps, int lane) {
    float4 wv = ((const float4*)w)[lane];
    float bv = b[0];
    for (int node = warpId; node < n; node += nWarps) {
        const __nv_bfloat162* ph = (const __nv_bfloat162*)(h2h + (size_t)node * HH + lane * 4);
        const __nv_bfloat162* pl = (const __nv_bfloat162*)(h2l + (size_t)node * HH + lane * 4);
        __nv_bfloat162 hh0 = ph[0], hh1 = ph[1], ll0 = pl[0], ll1 = pl[1];
        float v0 = __bfloat162float(hh0.x) + __bfloat162float(ll0.x);
        float v1 = __bfloat162float(hh0.y) + __bfloat162float(ll0.y);
        float v2 = __bfloat162float(hh1.x) + __bfloat162float(ll1.x);
        float v3 = __bfloat162float(hh1.y) + __bfloat162float(ll1.y);
        float s = v0 * wv.x + v1 * wv.y + v2 * wv.z + v3 * wv.w;
#pragma unroll
        for (int off = 16; off; off >>= 1) s += __shfl_xor_sync(0xFFFFFFFFu, s, off);
        if (lane == 0) out[node] = s + bv;
    }
}

template<bool LSTM>
__global__ void __launch_bounds__(256) mma_gemm_kernel(
    int M, int Nt, int K, GemmPtrs P, float* Cout) {
    extern __shared__ char smemc[];
    gemm_core<LSTM>(M, Nt, K, P, Cout, smemc);
}

// merged launch: z < nGemm -> GEMM slice (z==0 -> PA, z==1 -> PB);
// z == nGemm -> out_proj of the PREVIOUS timestep (planes already final).
__global__ void __launch_bounds__(256) lstm_pair_kernel(
    int M, int nGemm, GemmPtrs PA, GemmPtrs PB,
    const __nv_bfloat16* oph, const __nv_bfloat16* opl,
    const float* ow, const float* ob, float* ovec) {
    extern __shared__ char smemc[];
    if ((int)blockIdx.z >= nGemm) {
        const int bid = blockIdx.y * gridDim.x + blockIdx.x;
        const int warpId = bid * (blockDim.x >> 5) + (threadIdx.x >> 5);
        const int nWarps = gridDim.x * gridDim.y * (blockDim.x >> 5);
        out_proj_body(oph, opl, ow, ob, ovec, M, warpId, nWarps, threadIdx.x & 31);
        return;
    }
    gemm_core<true>(M, G4, 256, blockIdx.z ? PB : PA, nullptr, smemc);
}

// standalone out_proj (final timestep)
__global__ void out_proj_kernel(const __nv_bfloat16* __restrict__ h2h,
                                const __nv_bfloat16* __restrict__ h2l,
                                const float* __restrict__ w,
                                const float* __restrict__ b, float* __restrict__ out, int n) {
    int warpId = (blockIdx.x * blockDim.x + threadIdx.x) >> 5;
    int nWarps = (gridDim.x * blockDim.x) >> 5;
    out_proj_body(h2h, h2l, w, b, out, n, warpId, nWarps, threadIdx.x & 31);
}

__global__ void copy_states_kernel(const float* __restrict__ st, float* __restrict__ out, size_t nh) {
    size_t i = (size_t)blockIdx.x * blockDim.x + threadIdx.x;
    size_t total = 4 * nh;
    for (; i < total; i += (size_t)gridDim.x * blockDim.x) out[i] = st[i];
}

// ---------------- host launch ----------------
static inline int cdiv(int a, int b) { return (a + b - 1) / b; }
#define SYM(var, sym) cudaGetSymbolAddress((void**)&var, sym)

extern "C" void kernel_launch(void* const* d_in, const int* in_sizes, int n_in,
                              void* d_out, int out_size) {
    const float* x    = (const float*)d_in[0];
    const void*  ei   = d_in[1];
    const float* gw1  = (const float*)d_in[2];
    const float* gb1  = (const float*)d_in[3];
    const float* gw2  = (const float*)d_in[4];
    const float* gb2  = (const float*)d_in[5];
    const float* wih1 = (const float*)d_in[6];
    const float* whh1 = (const float*)d_in[7];
    const float* bih1 = (const float*)d_in[8];
    const float* bhh1 = (const float*)d_in[9];
    const float* wih2 = (const float*)d_in[10];
    const float* whh2 = (const float*)d_in[11];
    const float* bih2 = (const float*)d_in[12];
    const float* bhh2 = (const float*)d_in[13];
    const float* outw = (const float*)d_in[14];
    const float* outb = (const float*)d_in[15];

    const int N = in_sizes[0] / (TT * FIN);
    const int E = in_sizes[1] / (2 * TT);
    float* out = (float*)d_out;

    __nv_bfloat16 *xh, *xl, *fh, *fl, *b2h, *b2l;
    __nv_bfloat16 *h1h_a, *h1l_a, *h1h_b, *h1l_b, *h2h_a, *h2l_a, *h2h_b, *h2l_b;
    __nv_bfloat16 *B1h, *B1l, *B2h, *B2l, *GW1h, *GW1l, *GW2h, *GW2l;
    float *nis, *hlin, *state, *bias1, *bias2;
    int *offs, *cursor, *csr;
    SYM(xh, g_xh); SYM(xl, g_xl); SYM(fh, g_fh); SYM(fl, g_fl);
    SYM(b2h, g_b2h); SYM(b2l, g_b2l);
    SYM(h1h_a, g_h1h_a); SYM(h1l_a, g_h1l_a); SYM(h1h_b, g_h1h_b); SYM(h1l_b, g_h1l_b);
    SYM(h2h_a, g_h2h_a); SYM(h2l_a, g_h2l_a); SYM(h2h_b, g_h2h_b); SYM(h2l_b, g_h2l_b);
    SYM(B1h, g_B1h); SYM(B1l, g_B1l); SYM(B2h, g_B2h); SYM(B2l, g_B2l);
    SYM(GW1h, g_GW1h); SYM(GW1l, g_GW1l); SYM(GW2h, g_GW2h); SYM(GW2l, g_GW2l);
    SYM(nis, g_nis); SYM(hlin, g_hlin);
    SYM(offs, g_offs); SYM(cursor, g_cursor); SYM(csr, g_csr);
    SYM(state, g_state); SYM(bias1, g_bias1); SYM(bias2, g_bias2);

    const size_t NH = (size_t)N * HH;
    const long long TN = (long long)TT * N;

    const int mbA = (int)((TN + BM - 1) / BM);  // 3125
    const int mbL = cdiv(N, BM);                // 391
    const int gx = cdiv(cdiv(N, 2) * 32, 256);  // gather grid.x (2 nodes/warp)

    cudaFuncSetAttribute(mma_gemm_kernel<false>, cudaFuncAttributeMaxDynamicSharedMemorySize, GSMEM);
    cudaFuncSetAttribute(mma_gemm_kernel<true>,  cudaFuncAttributeMaxDynamicSharedMemorySize, GSMEM);
    cudaFuncSetAttribute(lstm_pair_kernel,       cudaFuncAttributeMaxDynamicSharedMemorySize, GSMEM);

    GemmPtrs P{};

    // launch order keeps GCN L1 GEMM at #5 (ncu sentinel across rounds)
    detect_idx_kernel<<<1, 1>>>(ei);                                            // 1
    prep_weights_kernel<<<cdiv(512 * 256, 256), 256>>>(gw1, gw2, wih1, whh1,    // 2
                                                       bih1, bhh1, wih2, whh2, bih2, bhh2);
    split_x_kernel<<<2048, 256>>>(x, (size_t)TN * FIN);                         // 3
    cudaMemsetAsync(nis, 0, TN * sizeof(float));                                // 4

    // -------- GCN layer 1 GEMM (batched over all t) --------                  // 5
    P = GemmPtrs{xh, xl, nullptr, nullptr, GW1h, GW1l, gb1, nullptr, nullptr, nullptr, nullptr};
    mma_gemm_kernel<false><<<dim3(1, mbA), 256, GSMEM>>>((int)TN, HH, 128, P, hlin);

    // -------- degrees -> CSR offsets -> fill -> nis --------
    deg_all_kernel<<<(unsigned)(((long long)TT * E + 255) / 256), 256>>>(ei, E, N, nis);
    scan_offsets_kernel<<<TT, 1024>>>(nis, offs, N);
    cudaMemsetAsync(cursor, 0, (size_t)TT * N * sizeof(int));
    csr_fill_kernel<<<(unsigned)(((long long)TT * E + 255) / 256), 256>>>(ei, E, N, offs, cursor, csr);
    nis_all_kernel<<<(unsigned)((TN + 255) / 256), 256>>>(nis, TN);

    // -------- GCN layer 1 gather (batched over t, 2 nodes/warp) --------
    gather_combine_all_kernel<<<dim3(gx, TT), 256>>>(csr, offs, nis, hlin, b2h, b2l, N, E);

    // -------- GCN layer 2 --------
    P = GemmPtrs{b2h, b2l, nullptr, nullptr, GW2h, GW2l, gb2, nullptr, nullptr, nullptr, nullptr};
    mma_gemm_kernel<false><<<dim3(1, mbA), 256, GSMEM>>>((int)TN, HH, 128, P, hlin);
    gather_combine_all_kernel<<<dim3(gx, TT), 256>>>(csr, offs, nis, hlin, fh, fl, N, E);

    // -------- LSTM over time (merged pairs + folded out_proj slices) --------
    cudaMemsetAsync(state, 0, 4 * NH * sizeof(float));
    cudaMemsetAsync(h1h_a, 0, NH * sizeof(__nv_bfloat16));
    cudaMemsetAsync(h1l_a, 0, NH * sizeof(__nv_bfloat16));
    cudaMemsetAsync(h2h_a, 0, NH * sizeof(__nv_bfloat16));
    cudaMemsetAsync(h2l_a, 0, NH * sizeof(__nv_bfloat16));

    float* h1a = state;               // final h1 (t=7 odd writes A bufs)
    float* c1  = state + NH;
    float* h2a = state + 2 * NH;
    float* c2  = state + 3 * NH;

    auto L1ptrs = [&](int t) -> GemmPtrs {
        const int odd = t & 1;
        return GemmPtrs{
            fh + (size_t)t * NH, fl + (size_t)t * NH,
            odd ? h1h_b : h1h_a, odd ? h1l_b : h1l_a,   // h1_{t-1} in
            B1h, B1l, bias1, c1,
            (t == TT - 1) ? h1a : nullptr,
            odd ? h1h_a : h1h_b, odd ? h1l_a : h1l_b};  // h1_t out
    };
    auto L2ptrs = [&](int t) -> GemmPtrs {
        const int odd = t & 1;
        return GemmPtrs{
            odd ? h1h_a : h1h_b, odd ? h1l_a : h1l_b,   // h1_t in
            odd ? h2h_b : h2h_a, odd ? h2l_b : h2l_a,   // h2_{t-1} in
            B2h, B2l, bias2, c2,
            (t == TT - 1) ? h2a : nullptr,
            odd ? h2h_a : h2h_b, odd ? h2l_a : h2l_b};  // h2_t out
    };
    auto h2h_of = [&](int t) { return (t & 1) ? h2h_a : h2h_b; };
    auto h2l_of = [&](int t) { return (t & 1) ? h2l_a : h2l_b; };

    // t=0 layer 1
    mma_gemm_kernel<true><<<dim3(4, mbL), 256, GSMEM>>>(N, G4, 256, L1ptrs(0), nullptr);
    for (int t = 0; t < TT; t++) {
        const bool hasOp = (t >= 1);   // out_proj(t-1) rides along
        const __nv_bfloat16* oph = hasOp ? h2h_of(t - 1) : nullptr;
        const __nv_bfloat16* opl = hasOp ? h2l_of(t - 1) : nullptr;
        float* ovec = hasOp ? out + (size_t)(t - 1) * N : nullptr;
        if (t + 1 < TT) {
            // z0: layer2(t), z1: layer1(t+1), z2 (if hasOp): out_proj(t-1)
            lstm_pair_kernel<<<dim3(4, mbL, hasOp ? 3 : 2), 256, GSMEM>>>(
                N, 2, L2ptrs(t), L1ptrs(t + 1), oph, opl, outw, outb, ovec);
        } else {
            // final: z0: layer2(7), z1: out_proj(6)
            lstm_pair_kernel<<<dim3(4, mbL, 2), 256, GSMEM>>>(
                N, 1, L2ptrs(t), L2ptrs(t), oph, opl, outw, outb, ovec);
        }
    }
    // out_proj(7)
    out_proj_kernel<<<cdiv(N * 32, 256), 256>>>(h2h_of(TT - 1), h2l_of(TT - 1),
                                                outw, outb, out + (size_t)(TT - 1) * N, N);

    // -------- tail: h1, c1, h2, c2 (t=7 odd -> finals in buf A = state) ------
    copy_states_kernel<<<1024, 256>>>(state, out + (size_t)TT * N, NH);
}